// round 1
// baseline (speedup 1.0000x reference)
#include <cuda_runtime.h>
#include <math.h>

#define BB 128
#define MM 64
#define DD 512
#define KK 4096
#define CC 64

#define FSTRIDE 64
#define CSTRIDE 129
#define SIMSTRIDE 65
#define SSTRIDE 68

// scratch (allocation-free rule: __device__ globals)
__device__ float g_w[BB*MM];
__device__ float g_lp[BB*MM];
__device__ float g_evi[BB*MM*CC];

// ---------------------------------------------------------------------------
// K1: soft-topk weights w and clamped log(P_sup). One block per batch, 64 thr.
// ---------------------------------------------------------------------------
__global__ void k_weights(const float* __restrict__ slot_prob,
                          const float* __restrict__ slot_mask) {
    int b = blockIdx.x, m = threadIdx.x;
    __shared__ float sv[MM];
    __shared__ float red[MM];
    __shared__ int   topi[3];
    __shared__ float s_mean, s_zmax, s_zsum, s_wsum, s_tmax, s_tsum;

    float mask = slot_mask[m];
    float pv = slot_prob[b*MM + m] * mask;
    sv[m] = pv;
    __syncthreads();
    if (m == 0) {
        for (int t = 0; t < 3; t++) {
            float best = -INFINITY; int bi = 0;
            for (int i = 0; i < MM; i++) if (sv[i] > best) { best = sv[i]; bi = i; }
            topi[t] = bi; sv[bi] = -INFINITY;
        }
    }
    __syncthreads();
    float keep = (m == topi[0] || m == topi[1] || m == topi[2]) ? 1.f : 0.f;
    float q = pv * keep;
    red[m] = q; __syncthreads();
    if (m == 0) { float s = 0.f; for (int i = 0; i < MM; i++) s += red[i]; s_mean = s / (float)MM; }
    __syncthreads();
    float z = (q - s_mean) * 2.0f;              // / beta (0.5)
    red[m] = z; __syncthreads();
    if (m == 0) { float mx = -INFINITY; for (int i = 0; i < MM; i++) mx = fmaxf(mx, red[i]); s_zmax = mx; }
    __syncthreads();
    float e = expf(z - s_zmax);
    red[m] = e; __syncthreads();
    if (m == 0) { float s = 0.f; for (int i = 0; i < MM; i++) s += red[i]; s_zsum = s; }
    __syncthreads();
    float w = (e / s_zsum) * mask;
    red[m] = w; __syncthreads();
    if (m == 0) { float s = 0.f; for (int i = 0; i < MM; i++) s += red[i]; s_wsum = s; }
    __syncthreads();
    w = w / fmaxf(s_wsum, 1e-8f);
    g_w[b*MM + m] = w;

    // P_sup = softmax(log(w+1e-8)/1.6); store log(max(P_sup,1e-8))
    float t = logf(w + 1e-8f) * (1.0f/1.6f);
    red[m] = t; __syncthreads();
    if (m == 0) { float mx = -INFINITY; for (int i = 0; i < MM; i++) mx = fmaxf(mx, red[i]); s_tmax = mx; }
    __syncthreads();
    float et = expf(t - s_tmax);
    red[m] = et; __syncthreads();
    if (m == 0) { float s = 0.f; for (int i = 0; i < MM; i++) s += red[i]; s_tsum = s; }
    __syncthreads();
    float lp = t - s_tmax - logf(s_tsum);
    g_lp[b*MM + m] = fmaxf(lp, -18.420680744f);   // log(1e-8)
}

// ---------------------------------------------------------------------------
// K2: fused l2norm + sim GEMM + per-class online LSE -> evi (B,M,64).
// One block per batch, 256 threads. f (normalized, transposed) resident in
// SMEM; C streamed in 64-proto x 128-d quarters. 4x4 register tiles.
// ---------------------------------------------------------------------------
__global__ void __launch_bounds__(256, 1)
k_evi(const float* __restrict__ feats,
      const float* __restrict__ Cmat,
      const int*   __restrict__ Ccls) {
    extern __shared__ float sm[];
    float* f_s    = sm;                       // [512][64] transposed (d-major)
    float* c_s    = f_s    + DD*FSTRIDE;      // [64][129]
    float* sim_s  = c_s    + 64*CSTRIDE;      // [64][65]
    float* lmax_s = sim_s  + 64*SIMSTRIDE;    // [64][65]
    float* lsum_s = lmax_s + 64*SIMSTRIDE;    // [64][65]
    int*   cls_s  = (int*)(lsum_s + 64*SIMSTRIDE); // [64]

    int b = blockIdx.x, tid = threadIdx.x;
    int wid = tid >> 5, lane = tid & 31;

    for (int i = tid; i < 64*SIMSTRIDE; i += 256) { lmax_s[i] = -INFINITY; lsum_s[i] = 0.f; }

    // normalize feats rows, store transposed
    const float* fb = feats + (size_t)b*MM*DD;
    for (int rr = 0; rr < 8; rr++) {
        int r = wid*8 + rr;
        const float4* rp = (const float4*)(fb + r*DD);
        float4 v[4]; float ss = 0.f;
        #pragma unroll
        for (int u = 0; u < 4; u++) {
            v[u] = rp[u*32 + lane];
            ss += v[u].x*v[u].x + v[u].y*v[u].y + v[u].z*v[u].z + v[u].w*v[u].w;
        }
        #pragma unroll
        for (int o = 16; o > 0; o >>= 1) ss += __shfl_xor_sync(0xffffffffu, ss, o);
        float inv = 1.0f / fmaxf(sqrtf(ss), 1e-12f);
        #pragma unroll
        for (int u = 0; u < 4; u++) {
            int d0 = u*128 + lane*4;
            f_s[(d0+0)*FSTRIDE + r] = v[u].x * inv;
            f_s[(d0+1)*FSTRIDE + r] = v[u].y * inv;
            f_s[(d0+2)*FSTRIDE + r] = v[u].z * inv;
            f_s[(d0+3)*FSTRIDE + r] = v[u].w * inv;
        }
    }

    int tr = tid >> 4, tc = tid & 15;          // GEMM tile coords
    int r  = tid >> 2, qg = tid & 3;           // LSE ownership: row r, class group qg
    int cbase = qg * 16;
    int cp_p = tid >> 2, cp_q = tid & 3;       // C-load mapping

    for (int kt = 0; kt < KK/64; kt++) {
        float acc[4][4] = {};
        #pragma unroll 1
        for (int h = 0; h < 4; h++) {
            __syncthreads();
            {
                const float4* cp = (const float4*)(Cmat + ((size_t)(kt*64 + cp_p))*DD + h*128 + cp_q*4);
                float* cw = c_s + cp_p*CSTRIDE + cp_q*4;
                #pragma unroll
                for (int u = 0; u < 8; u++) {
                    float4 cv = cp[u*4];
                    cw[u*16 + 0] = cv.x; cw[u*16 + 1] = cv.y;
                    cw[u*16 + 2] = cv.z; cw[u*16 + 3] = cv.w;
                }
            }
            if (h == 0 && tid < 64) cls_s[tid] = Ccls[kt*64 + tid];
            __syncthreads();
            const float* fp = f_s + h*128*FSTRIDE + tr*4;
            const float* cb = c_s + (tc*4)*CSTRIDE;
            #pragma unroll 4
            for (int k = 0; k < 128; k++) {
                float4 fv = *(const float4*)(fp + k*FSTRIDE);
                #pragma unroll
                for (int j = 0; j < 4; j++) {
                    float cj = cb[j*CSTRIDE + k];
                    acc[0][j] = fmaf(fv.x, cj, acc[0][j]);
                    acc[1][j] = fmaf(fv.y, cj, acc[1][j]);
                    acc[2][j] = fmaf(fv.z, cj, acc[2][j]);
                    acc[3][j] = fmaf(fv.w, cj, acc[3][j]);
                }
            }
        }
        __syncthreads();
        #pragma unroll
        for (int i = 0; i < 4; i++)
            #pragma unroll
            for (int j = 0; j < 4; j++)
                sim_s[(tr*4 + i)*SIMSTRIDE + tc*4 + j] = acc[i][j];
        __syncthreads();
        // online segmented LSE (tau = 0.5 -> exponent * 2)
        for (int p = 0; p < 64; p++) {
            int c = cls_s[p] - cbase;
            if ((unsigned)c < 16u) {
                int idx = r*SIMSTRIDE + cbase + c;
                float s  = sim_s[r*SIMSTRIDE + p];
                float mo = lmax_s[idx];
                float so = lsum_s[idx];
                if (s > mo) { so = so * __expf((mo - s) * 2.0f) + 1.0f; mo = s; }
                else        { so += __expf((s - mo) * 2.0f); }
                lmax_s[idx] = mo;
                lsum_s[idx] = so;
            }
        }
    }
    __syncthreads();
    for (int cc = 0; cc < 16; cc++) {
        int c = cbase + cc;
        float mo = lmax_s[r*SIMSTRIDE + c];
        float so = lsum_s[r*SIMSTRIDE + c];
        g_evi[((size_t)b*MM + r)*CC + c] = mo + 0.5f * logf(fmaxf(so, 1e-8f));
    }
}

// ---------------------------------------------------------------------------
// K3: epilogue per batch: top1, normalized slot cosines vs top1 slots,
// support LSE, final logits. One block per batch, 256 threads.
// ---------------------------------------------------------------------------
__global__ void __launch_bounds__(256, 1)
k_out(const float* __restrict__ S_slots,
      const float* __restrict__ alpha,
      float* __restrict__ out) {
    extern __shared__ float sm[];
    float* s_s   = sm;                        // [512][68] normalized S, transposed
    float* tf_s  = s_s  + DD*SSTRIDE;         // [256][68] gathered top1 cols; reused as sup_s
    float* evi_s = tf_s + 256*SSTRIDE;        // [64*64]
    float* w_s   = evi_s + MM*CC;             // [64]
    float* lp_s  = w_s + MM;                  // [64]
    float* t1v   = lp_s + MM;                 // [64]
    int*   t1i   = (int*)(t1v + MM);          // [64]

    int b = blockIdx.x, tid = threadIdx.x;
    int wid = tid >> 5, lane = tid & 31;

    for (int i = tid; i < MM*CC; i += 256) evi_s[i] = g_evi[(size_t)b*MM*CC + i];
    if (tid < MM) { w_s[tid] = g_w[b*MM + tid]; lp_s[tid] = g_lp[b*MM + tid]; }

    // normalize S rows, store transposed
    const float* sb = S_slots + (size_t)b*MM*DD;
    for (int rr = 0; rr < 8; rr++) {
        int r = wid*8 + rr;
        const float4* rp = (const float4*)(sb + r*DD);
        float4 v[4]; float ss = 0.f;
        #pragma unroll
        for (int u = 0; u < 4; u++) {
            v[u] = rp[u*32 + lane];
            ss += v[u].x*v[u].x + v[u].y*v[u].y + v[u].z*v[u].z + v[u].w*v[u].w;
        }
        #pragma unroll
        for (int o = 16; o > 0; o >>= 1) ss += __shfl_xor_sync(0xffffffffu, ss, o);
        float inv = 1.0f / fmaxf(sqrtf(ss), 1e-12f);
        #pragma unroll
        for (int u = 0; u < 4; u++) {
            int d0 = u*128 + lane*4;
            s_s[(d0+0)*SSTRIDE + r] = v[u].x * inv;
            s_s[(d0+1)*SSTRIDE + r] = v[u].y * inv;
            s_s[(d0+2)*SSTRIDE + r] = v[u].z * inv;
            s_s[(d0+3)*SSTRIDE + r] = v[u].w * inv;
        }
    }
    __syncthreads();

    // top1 over slots per class: score = evi * w
    if (tid < CC) {
        int c = tid;
        float best = -INFINITY; int bi = 0;
        for (int m = 0; m < MM; m++) {
            float sc = evi_s[m*CC + c] * w_s[m];
            if (sc > best) { best = sc; bi = m; }
        }
        t1v[c] = best; t1i[c] = bi;
    }
    __syncthreads();

    // cos(m,c) = S_n[m] . S_n[top1[c]]  — 64x64x512 GEMM, 4x4 tiles
    int tr = tid >> 4, tc = tid & 15;
    int gc = tid >> 2, gq = tid & 3;
    float acc[4][4] = {};
    #pragma unroll 1
    for (int h = 0; h < 2; h++) {
        __syncthreads();
        {
            int src = t1i[gc];
            for (int u = 0; u < 64; u++) {
                int k = gq*64 + u;
                tf_s[k*SSTRIDE + gc] = s_s[(h*256 + k)*SSTRIDE + src];
            }
        }
        __syncthreads();
        const float* fp = s_s  + h*256*SSTRIDE + tr*4;
        const float* gp = tf_s + tc*4;
        #pragma unroll 4
        for (int k = 0; k < 256; k++) {
            float4 fv = *(const float4*)(fp + k*SSTRIDE);
            float4 gv = *(const float4*)(gp + k*SSTRIDE);
            acc[0][0] = fmaf(fv.x, gv.x, acc[0][0]);
            acc[0][1] = fmaf(fv.x, gv.y, acc[0][1]);
            acc[0][2] = fmaf(fv.x, gv.z, acc[0][2]);
            acc[0][3] = fmaf(fv.x, gv.w, acc[0][3]);
            acc[1][0] = fmaf(fv.y, gv.x, acc[1][0]);
            acc[1][1] = fmaf(fv.y, gv.y, acc[1][1]);
            acc[1][2] = fmaf(fv.y, gv.z, acc[1][2]);
            acc[1][3] = fmaf(fv.y, gv.w, acc[1][3]);
            acc[2][0] = fmaf(fv.z, gv.x, acc[2][0]);
            acc[2][1] = fmaf(fv.z, gv.y, acc[2][1]);
            acc[2][2] = fmaf(fv.z, gv.z, acc[2][2]);
            acc[2][3] = fmaf(fv.z, gv.w, acc[2][3]);
            acc[3][0] = fmaf(fv.w, gv.x, acc[3][0]);
            acc[3][1] = fmaf(fv.w, gv.y, acc[3][1]);
            acc[3][2] = fmaf(fv.w, gv.z, acc[3][2]);
            acc[3][3] = fmaf(fv.w, gv.w, acc[3][3]);
        }
    }
    __syncthreads();
    float* sup_s = tf_s;    // reuse
    #pragma unroll
    for (int i = 0; i < 4; i++) {
        #pragma unroll
        for (int j = 0; j < 4; j++) {
            int m = tr*4 + i, c = tc*4 + j;
            float cosv = fmaxf(acc[i][j], 0.f);
            float sr = evi_s[m*CC + c] + lp_s[m] - cosv;   // kappa_feat = 1
            if (m == t1i[c]) sr = -10000.0f;
            sup_s[m*CC + c] = sr;
        }
    }
    __syncthreads();
    if (tid < CC) {
        int c = tid;
        float mx = -INFINITY;
        for (int m = 0; m < MM; m++) mx = fmaxf(mx, sup_s[m*CC + c]);
        float sum = 0.f;
        for (int m = 0; m < MM; m++) sum += expf(sup_s[m*CC + c] - mx);
        float sval = mx + logf(sum);
        out[b*CC + c] = alpha[0] * (t1v[c] + 0.4f * sval);   // beta_sup = 0.4
    }
}

// ---------------------------------------------------------------------------
extern "C" void kernel_launch(void* const* d_in, const int* in_sizes, int n_in,
                              void* d_out, int out_size) {
    const float* feats     = (const float*)d_in[0];
    const float* slot_prob = (const float*)d_in[1];
    const float* slot_mask = (const float*)d_in[2];
    const float* S_slots   = (const float*)d_in[3];
    const float* Cmat      = (const float*)d_in[4];
    const int*   Ccls      = (const int*)d_in[5];
    const float* alpha     = (const float*)d_in[6];
    float* out = (float*)d_out;

    const int smem2 = (DD*FSTRIDE + 64*CSTRIDE + 3*64*SIMSTRIDE) * 4 + 64 * 4;
    const int smem3 = (DD*SSTRIDE + 256*SSTRIDE + MM*CC + 3*MM) * 4 + MM * 4;

    cudaFuncSetAttribute(k_evi, cudaFuncAttributeMaxDynamicSharedMemorySize, smem2);
    cudaFuncSetAttribute(k_out, cudaFuncAttributeMaxDynamicSharedMemorySize, smem3);

    k_weights<<<BB, MM>>>(slot_prob, slot_mask);
    k_evi<<<BB, 256, smem2>>>(feats, Cmat, Ccls);
    k_out<<<BB, 256, smem3>>>(S_slots, alpha, out);
}

// round 3
// speedup vs baseline: 2.4943x; 2.4943x over previous
#include <cuda_runtime.h>
#include <cuda_bf16.h>
#include <math.h>
#include <stdint.h>

#define BB 128
#define MM 64
#define DD 512
#define KK 4096
#define CC 64
#define SSTRIDE 68

// ---------------------------------------------------------------------------
// scratch (__device__ globals per allocation-free rule)
// ---------------------------------------------------------------------------
__device__ __align__(16) __nv_bfloat16 g_F1[BB*MM*DD];
__device__ __align__(16) __nv_bfloat16 g_F2[BB*MM*DD];
__device__ __align__(16) __nv_bfloat16 g_C1[KK*DD];
__device__ __align__(16) __nv_bfloat16 g_C2[KK*DD];
__device__ float g_evi[BB*MM*CC];
__device__ float g_w[BB*MM];
__device__ float g_lp[BB*MM];

// ---------------------------------------------------------------------------
__device__ __forceinline__ uint32_t smem_to_u32(const void* p) {
    uint32_t a;
    asm("{ .reg .u64 t; cvta.to.shared.u64 t, %1; cvt.u32.u64 %0, t; }" : "=r"(a) : "l"(p));
    return a;
}
__device__ __forceinline__ void cp16(uint32_t dst, const void* src) {
    asm volatile("cp.async.cg.shared.global [%0], [%1], 16;" :: "r"(dst), "l"(src));
}
__device__ __forceinline__ void cp_commit() { asm volatile("cp.async.commit_group;" ::: "memory"); }
__device__ __forceinline__ void cp_wait0()  { asm volatile("cp.async.wait_group 0;" ::: "memory"); }
__device__ __forceinline__ void cp_wait1()  { asm volatile("cp.async.wait_group 1;" ::: "memory"); }

__device__ __forceinline__ void ldm_x4(uint32_t r[4], uint32_t addr) {
    asm volatile("ldmatrix.sync.aligned.m8n8.x4.shared.b16 {%0,%1,%2,%3}, [%4];"
        : "=r"(r[0]), "=r"(r[1]), "=r"(r[2]), "=r"(r[3]) : "r"(addr));
}
__device__ __forceinline__ void mma16816(float* c, const uint32_t* a, uint32_t b0, uint32_t b1) {
    asm volatile(
        "mma.sync.aligned.m16n8k16.row.col.f32.bf16.bf16.f32 "
        "{%0,%1,%2,%3}, {%4,%5,%6,%7}, {%8,%9}, {%0,%1,%2,%3};"
        : "+f"(c[0]), "+f"(c[1]), "+f"(c[2]), "+f"(c[3])
        : "r"(a[0]), "r"(a[1]), "r"(a[2]), "r"(a[3]), "r"(b0), "r"(b1));
}

// ---------------------------------------------------------------------------
// bf16 two-term split helpers
// ---------------------------------------------------------------------------
__device__ __forceinline__ void split4(float4 v, uint2& w1, uint2& w2) {
    __nv_bfloat162 a = __floats2bfloat162_rn(v.x, v.y);
    __nv_bfloat162 b = __floats2bfloat162_rn(v.z, v.w);
    float rx = v.x - __bfloat162float(__low2bfloat16(a));
    float ry = v.y - __bfloat162float(__high2bfloat16(a));
    float rz = v.z - __bfloat162float(__low2bfloat16(b));
    float rw = v.w - __bfloat162float(__high2bfloat16(b));
    __nv_bfloat162 a2 = __floats2bfloat162_rn(rx, ry);
    __nv_bfloat162 b2 = __floats2bfloat162_rn(rz, rw);
    w1.x = *(uint32_t*)&a;  w1.y = *(uint32_t*)&b;
    w2.x = *(uint32_t*)&a2; w2.y = *(uint32_t*)&b2;
}

__global__ void prep_C(const float* __restrict__ Cmat) {
    int idx = blockIdx.x * 256 + threadIdx.x;             // over float4s
    float4 v = ((const float4*)Cmat)[idx];
    uint2 w1, w2; split4(v, w1, w2);
    ((uint2*)g_C1)[idx] = w1;
    ((uint2*)g_C2)[idx] = w2;
}

__global__ void prep_F(const float* __restrict__ feats) {
    int row = blockIdx.x * 8 + (threadIdx.x >> 5);
    int lane = threadIdx.x & 31;
    const float4* rp = (const float4*)(feats + (size_t)row * DD);
    float4 v[4]; float ss = 0.f;
    #pragma unroll
    for (int u = 0; u < 4; u++) {
        v[u] = rp[lane + u*32];
        ss += v[u].x*v[u].x + v[u].y*v[u].y + v[u].z*v[u].z + v[u].w*v[u].w;
    }
    #pragma unroll
    for (int o = 16; o > 0; o >>= 1) ss += __shfl_xor_sync(0xffffffffu, ss, o);
    float inv = 1.0f / fmaxf(sqrtf(ss), 1e-12f);
    #pragma unroll
    for (int u = 0; u < 4; u++) {
        float4 f = make_float4(v[u].x*inv, v[u].y*inv, v[u].z*inv, v[u].w*inv);
        uint2 w1, w2; split4(f, w1, w2);
        ((uint2*)(g_F1 + (size_t)row * DD))[lane + u*32] = w1;
        ((uint2*)(g_F2 + (size_t)row * DD))[lane + u*32] = w2;
    }
}

// ---------------------------------------------------------------------------
// K1: soft-topk weights + log(P_sup)
// ---------------------------------------------------------------------------
__global__ void k_weights(const float* __restrict__ slot_prob,
                          const float* __restrict__ slot_mask) {
    int b = blockIdx.x, m = threadIdx.x;
    __shared__ float sv[MM];
    __shared__ float red[MM];
    __shared__ int   topi[3];
    __shared__ float s_mean, s_zmax, s_zsum, s_wsum, s_tmax, s_tsum;

    float mask = slot_mask[m];
    float pv = slot_prob[b*MM + m] * mask;
    sv[m] = pv;
    __syncthreads();
    if (m == 0) {
        for (int t = 0; t < 3; t++) {
            float best = -INFINITY; int bi = 0;
            for (int i = 0; i < MM; i++) if (sv[i] > best) { best = sv[i]; bi = i; }
            topi[t] = bi; sv[bi] = -INFINITY;
        }
    }
    __syncthreads();
    float keep = (m == topi[0] || m == topi[1] || m == topi[2]) ? 1.f : 0.f;
    float q = pv * keep;
    red[m] = q; __syncthreads();
    if (m == 0) { float s = 0.f; for (int i = 0; i < MM; i++) s += red[i]; s_mean = s / (float)MM; }
    __syncthreads();
    float z = (q - s_mean) * 2.0f;
    red[m] = z; __syncthreads();
    if (m == 0) { float mx = -INFINITY; for (int i = 0; i < MM; i++) mx = fmaxf(mx, red[i]); s_zmax = mx; }
    __syncthreads();
    float e = expf(z - s_zmax);
    red[m] = e; __syncthreads();
    if (m == 0) { float s = 0.f; for (int i = 0; i < MM; i++) s += red[i]; s_zsum = s; }
    __syncthreads();
    float w = (e / s_zsum) * mask;
    red[m] = w; __syncthreads();
    if (m == 0) { float s = 0.f; for (int i = 0; i < MM; i++) s += red[i]; s_wsum = s; }
    __syncthreads();
    w = w / fmaxf(s_wsum, 1e-8f);
    g_w[b*MM + m] = w;

    float t = logf(w + 1e-8f) * (1.0f/1.6f);
    red[m] = t; __syncthreads();
    if (m == 0) { float mx = -INFINITY; for (int i = 0; i < MM; i++) mx = fmaxf(mx, red[i]); s_tmax = mx; }
    __syncthreads();
    float et = expf(t - s_tmax);
    red[m] = et; __syncthreads();
    if (m == 0) { float s = 0.f; for (int i = 0; i < MM; i++) s += red[i]; s_tsum = s; }
    __syncthreads();
    float lp = t - s_tmax - logf(s_tsum);
    g_lp[b*MM + m] = fmaxf(lp, -18.420680744f);
}

// ---------------------------------------------------------------------------
// K2: bf16x3 HMMA GEMM fused with segmented exp-sum. One CTA per batch.
// A1/A2 (64x512 bf16) resident; B1/B2 streamed in 64-proto x 64-d chunks.
// ---------------------------------------------------------------------------
#define ASTR 520            // bf16 elems per A row (padded)
#define BSTR 72             // bf16 elems per B row (padded)
#define OFF_A1 0u
#define OFF_A2 66560u
#define OFF_B  133120u      // [2 buf][2 split][64n x 72k] bf16
#define B_BUF  18432u
#define B_SPL  9216u
#define OFF_SIM 169984u     // [64][66] f32
#define OFF_SUM 186880u     // [64][65] f32
#define OFF_CLS 203520u     // [4096] u8
#define SMEM_EVI 207616

__device__ __forceinline__ void load_Bchunk(uint32_t base, int b_kt, int dc, int tid) {
    #pragma unroll
    for (int ii = 0; ii < 4; ii++) {
        int i = tid + ii*256;
        int split = i >> 9, n = (i >> 3) & 63, g = i & 7;
        const __nv_bfloat16* src = (split ? g_C2 : g_C1)
            + (size_t)(b_kt*64 + n)*DD + dc*64 + g*8;
        cp16(base + (uint32_t)split*B_SPL + (uint32_t)n*(BSTR*2) + (uint32_t)g*16, src);
    }
}

__global__ void __launch_bounds__(256, 1)
k_evi(const int* __restrict__ Ccls) {
    extern __shared__ __align__(1024) char smem[];
    uint32_t smem_base = smem_to_u32(smem);
    const int tid = threadIdx.x, wid = tid >> 5, lane = tid & 31;
    const int b = blockIdx.x;
    const int wr = wid & 3, wc = wid >> 2;     // warp 16-row block, 32-col block

    float*   sim_s = (float*)(smem + OFF_SIM);
    float*   sums  = (float*)(smem + OFF_SUM);
    uint8_t* cls_s = (uint8_t*)(smem + OFF_CLS);

    for (int i = tid; i < 64*65; i += 256) sums[i] = 0.f;
    for (int i = tid; i < KK; i += 256) cls_s[i] = (uint8_t)Ccls[i];

    // resident A: both splits, row-major stride 520
    #pragma unroll
    for (int ii = 0; ii < 32; ii++) {
        int i = tid + ii*256;
        int split = i >> 12, r = (i >> 6) & 63, g = i & 63;
        const __nv_bfloat16* src = (split ? g_F2 : g_F1) + ((size_t)b*MM + r)*DD + g*8;
        cp16(smem_base + (split ? OFF_A2 : OFF_A1) + (uint32_t)r*(ASTR*2) + (uint32_t)g*16, src);
    }
    cp_commit();

    load_Bchunk(smem_base + OFF_B, 0, 0, tid);
    cp_commit();

    // precomputed ldmatrix lane addressing
    const uint32_t aOff = (uint32_t)(wr*16 + (lane & 15))*(ASTR*2) + (uint32_t)(lane >> 4)*16;
    const uint32_t aBase1 = smem_base + OFF_A1 + aOff;
    const uint32_t aBase2 = smem_base + OFF_A2 + aOff;
    const uint32_t bLane = (uint32_t)((lane & 7) + ((lane >> 4) << 3))*(BSTR*2)
                         + (uint32_t)((lane >> 3) & 1)*16;

    const int r_lse = tid >> 2, qg = tid & 3, cbase = qg << 4;

    float acc[16];

    for (int q = 0; q < 512; ++q) {
        const int kt = q >> 3, dc = q & 7, buf = q & 1;
        if (q + 1 < 512) {
            load_Bchunk(smem_base + OFF_B + (uint32_t)((q+1)&1)*B_BUF, (q+1) >> 3, (q+1) & 7, tid);
            cp_commit();
            cp_wait1();
        } else {
            cp_wait0();
        }
        __syncthreads();

        if (dc == 0) {
            #pragma unroll
            for (int i = 0; i < 16; i++) acc[i] = 0.f;
        }

        const uint32_t bBuf = smem_base + OFF_B + (uint32_t)buf*B_BUF;
        #pragma unroll
        for (int ks = 0; ks < 4; ++ks) {
            uint32_t a1[4], a2[4];
            ldm_x4(a1, aBase1 + (uint32_t)(dc*64 + ks*16)*2);
            ldm_x4(a2, aBase2 + (uint32_t)(dc*64 + ks*16)*2);
            #pragma unroll
            for (int half = 0; half < 2; ++half) {
                uint32_t bAddr = bBuf + (uint32_t)(wc*32 + half*16)*(BSTR*2) + bLane + (uint32_t)ks*32;
                uint32_t b1[4], b2[4];
                ldm_x4(b1, bAddr);
                ldm_x4(b2, bAddr + B_SPL);
                float* c0 = acc + half*8;
                float* c1 = acc + half*8 + 4;
                mma16816(c0, a1, b1[0], b1[1]);
                mma16816(c1, a1, b1[2], b1[3]);
                mma16816(c0, a2, b1[0], b1[1]);
                mma16816(c1, a2, b1[2], b1[3]);
                mma16816(c0, a1, b2[0], b2[1]);
                mma16816(c1, a1, b2[2], b2[3]);
            }
        }

        if (dc == 7) {
            __syncthreads();
            // write sim tile 16x32 per warp
            int rA = wr*16 + (lane >> 2);
            int cA = (lane & 3)*2;
            #pragma unroll
            for (int t = 0; t < 4; ++t) {
                int n0 = wc*32 + t*8 + cA;
                sim_s[rA*66 + n0]       = acc[t*4 + 0];
                sim_s[rA*66 + n0 + 1]   = acc[t*4 + 1];
                sim_s[(rA+8)*66 + n0]   = acc[t*4 + 2];
                sim_s[(rA+8)*66 + n0+1] = acc[t*4 + 3];
            }
            __syncthreads();
            // segmented exp-sum (sum-only LSE, tau = 0.5)
            const uint8_t* cl = cls_s + kt*64;
            float* srow = sums + r_lse*65;
            const float* simr = sim_s + r_lse*66;
            #pragma unroll 4
            for (int p = 0; p < 64; ++p) {
                int c = (int)cl[p];
                if ((unsigned)(c - cbase) < 16u)
                    srow[c] += __expf(2.0f * simr[p]);
            }
            __syncthreads();
        }
    }

    // evi = tau * log(sum)
    {
        float* dst = g_evi + ((size_t)b*MM + r_lse)*CC;
        const float* srow = sums + r_lse*65;
        #pragma unroll
        for (int cc = 0; cc < 16; ++cc) {
            int c = cbase + cc;
            dst[c] = 0.5f * logf(fmaxf(srow[c], 1e-8f));
        }
    }
}

// ---------------------------------------------------------------------------
// K3: epilogue per batch (top1, cosines vs top1 slots, support LSE)
// ---------------------------------------------------------------------------
__global__ void __launch_bounds__(256, 1)
k_out(const float* __restrict__ S_slots,
      const float* __restrict__ alpha,
      float* __restrict__ out) {
    extern __shared__ float sm[];
    float* s_s   = sm;                        // [512][68]
    float* tf_s  = s_s  + DD*SSTRIDE;         // [256][68]; reused as sup_s
    float* evi_s = tf_s + 256*SSTRIDE;        // [64*64]
    float* w_s   = evi_s + MM*CC;
    float* lp_s  = w_s + MM;
    float* t1v   = lp_s + MM;
    int*   t1i   = (int*)(t1v + MM);

    int b = blockIdx.x, tid = threadIdx.x;
    int wid = tid >> 5, lane = tid & 31;

    for (int i = tid; i < MM*CC; i += 256) evi_s[i] = g_evi[(size_t)b*MM*CC + i];
    if (tid < MM) { w_s[tid] = g_w[b*MM + tid]; lp_s[tid] = g_lp[b*MM + tid]; }

    const float* sb = S_slots + (size_t)b*MM*DD;
    for (int rr = 0; rr < 8; rr++) {
        int r = wid*8 + rr;
        const float4* rp = (const float4*)(sb + r*DD);
        float4 v[4]; float ss = 0.f;
        #pragma unroll
        for (int u = 0; u < 4; u++) {
            v[u] = rp[u*32 + lane];
            ss += v[u].x*v[u].x + v[u].y*v[u].y + v[u].z*v[u].z + v[u].w*v[u].w;
        }
        #pragma unroll
        for (int o = 16; o > 0; o >>= 1) ss += __shfl_xor_sync(0xffffffffu, ss, o);
        float inv = 1.0f / fmaxf(sqrtf(ss), 1e-12f);
        #pragma unroll
        for (int u = 0; u < 4; u++) {
            int d0 = u*128 + lane*4;
            s_s[(d0+0)*SSTRIDE + r] = v[u].x * inv;
            s_s[(d0+1)*SSTRIDE + r] = v[u].y * inv;
            s_s[(d0+2)*SSTRIDE + r] = v[u].z * inv;
            s_s[(d0+3)*SSTRIDE + r] = v[u].w * inv;
        }
    }
    __syncthreads();

    if (tid < CC) {
        int c = tid;
        float best = -INFINITY; int bi = 0;
        for (int m = 0; m < MM; m++) {
            float sc = evi_s[m*CC + c] * w_s[m];
            if (sc > best) { best = sc; bi = m; }
        }
        t1v[c] = best; t1i[c] = bi;
    }
    __syncthreads();

    int tr = tid >> 4, tc = tid & 15;
    int gc = tid >> 2, gq = tid & 3;
    float acc[4][4] = {};
    #pragma unroll 1
    for (int h = 0; h < 2; h++) {
        __syncthreads();
        {
            int src = t1i[gc];
            for (int u = 0; u < 64; u++) {
                int k = gq*64 + u;
                tf_s[k*SSTRIDE + gc] = s_s[(h*256 + k)*SSTRIDE + src];
            }
        }
        __syncthreads();
        const float* fp = s_s  + h*256*SSTRIDE + tr*4;
        const float* gp = tf_s + tc*4;
        #pragma unroll 4
        for (int k = 0; k < 256; k++) {
            float4 fv = *(const float4*)(fp + k*SSTRIDE);
            float4 gv = *(const float4*)(gp + k*SSTRIDE);
            acc[0][0] = fmaf(fv.x, gv.x, acc[0][0]);
            acc[0][1] = fmaf(fv.x, gv.y, acc[0][1]);
            acc[0][2] = fmaf(fv.x, gv.z, acc[0][2]);
            acc[0][3] = fmaf(fv.x, gv.w, acc[0][3]);
            acc[1][0] = fmaf(fv.y, gv.x, acc[1][0]);
            acc[1][1] = fmaf(fv.y, gv.y, acc[1][1]);
            acc[1][2] = fmaf(fv.y, gv.z, acc[1][2]);
            acc[1][3] = fmaf(fv.y, gv.w, acc[1][3]);
            acc[2][0] = fmaf(fv.z, gv.x, acc[2][0]);
            acc[2][1] = fmaf(fv.z, gv.y, acc[2][1]);
            acc[2][2] = fmaf(fv.z, gv.z, acc[2][2]);
            acc[2][3] = fmaf(fv.z, gv.w, acc[2][3]);
            acc[3][0] = fmaf(fv.w, gv.x, acc[3][0]);
            acc[3][1] = fmaf(fv.w, gv.y, acc[3][1]);
            acc[3][2] = fmaf(fv.w, gv.z, acc[3][2]);
            acc[3][3] = fmaf(fv.w, gv.w, acc[3][3]);
        }
    }
    __syncthreads();
    float* sup_s = tf_s;
    #pragma unroll
    for (int i = 0; i < 4; i++) {
        #pragma unroll
        for (int j = 0; j < 4; j++) {
            int m = tr*4 + i, c = tc*4 + j;
            float cosv = fmaxf(acc[i][j], 0.f);
            float sr = evi_s[m*CC + c] + lp_s[m] - cosv;
            if (m == t1i[c]) sr = -10000.0f;
            sup_s[m*CC + c] = sr;
        }
    }
    __syncthreads();
    if (tid < CC) {
        int c = tid;
        float mx = -INFINITY;
        for (int m = 0; m < MM; m++) mx = fmaxf(mx, sup_s[m*CC + c]);
        float sum = 0.f;
        for (int m = 0; m < MM; m++) sum += expf(sup_s[m*CC + c] - mx);
        float sval = mx + logf(sum);
        out[b*CC + c] = alpha[0] * (t1v[c] + 0.4f * sval);
    }
}

// ---------------------------------------------------------------------------
extern "C" void kernel_launch(void* const* d_in, const int* in_sizes, int n_in,
                              void* d_out, int out_size) {
    const float* feats     = (const float*)d_in[0];
    const float* slot_prob = (const float*)d_in[1];
    const float* slot_mask = (const float*)d_in[2];
    const float* S_slots   = (const float*)d_in[3];
    const float* Cmat      = (const float*)d_in[4];
    const int*   Ccls      = (const int*)d_in[5];
    const float* alpha     = (const float*)d_in[6];
    float* out = (float*)d_out;

    const int smem3 = (DD*SSTRIDE + 256*SSTRIDE + MM*CC + 3*MM) * 4 + MM * 4;

    cudaFuncSetAttribute(k_evi, cudaFuncAttributeMaxDynamicSharedMemorySize, SMEM_EVI);
    cudaFuncSetAttribute(k_out, cudaFuncAttributeMaxDynamicSharedMemorySize, smem3);

    k_weights<<<BB, MM>>>(slot_prob, slot_mask);
    prep_F<<<BB*MM/8, 256>>>(feats);
    prep_C<<<KK*DD/1024, 256>>>(Cmat);
    k_evi<<<BB, 256, SMEM_EVI>>>(Ccls);
    k_out<<<BB, 256, smem3>>>(S_slots, alpha, out);
}

// round 4
// speedup vs baseline: 6.7430x; 2.7033x over previous
#include <cuda_runtime.h>
#include <cuda_fp16.h>
#include <math.h>
#include <stdint.h>

#define BB 128
#define MM 64
#define DD 512
#define KK 4096
#define CC 64
#define SSTRIDE 68

// ---------------------------------------------------------------------------
// scratch (__device__ globals per allocation-free rule)
// ---------------------------------------------------------------------------
__device__ __align__(16) __half g_Fh[BB*MM*DD];   // normalized feats, f16
__device__ __align__(16) __half g_Ch[KK*DD];      // C, f16, class-sorted rows
__device__ int     g_rank[KK];
__device__ uint8_t g_clsSorted[KK];
__device__ float   g_evi[BB*MM*CC];
__device__ float   g_w[BB*MM];
__device__ float   g_lp[BB*MM];

// ---------------------------------------------------------------------------
__device__ __forceinline__ uint32_t smem_to_u32(const void* p) {
    uint32_t a;
    asm("{ .reg .u64 t; cvta.to.shared.u64 t, %1; cvt.u32.u64 %0, t; }" : "=r"(a) : "l"(p));
    return a;
}
__device__ __forceinline__ void cp16(uint32_t dst, const void* src) {
    asm volatile("cp.async.cg.shared.global [%0], [%1], 16;" :: "r"(dst), "l"(src));
}
__device__ __forceinline__ void cp_commit() { asm volatile("cp.async.commit_group;" ::: "memory"); }
__device__ __forceinline__ void cp_wait0()  { asm volatile("cp.async.wait_group 0;" ::: "memory"); }
__device__ __forceinline__ void cp_wait1()  { asm volatile("cp.async.wait_group 1;" ::: "memory"); }

__device__ __forceinline__ void ldm_x4(uint32_t r[4], uint32_t addr) {
    asm volatile("ldmatrix.sync.aligned.m8n8.x4.shared.b16 {%0,%1,%2,%3}, [%4];"
        : "=r"(r[0]), "=r"(r[1]), "=r"(r[2]), "=r"(r[3]) : "r"(addr));
}
__device__ __forceinline__ void mma16816(float* c, const uint32_t* a, uint32_t b0, uint32_t b1) {
    asm volatile(
        "mma.sync.aligned.m16n8k16.row.col.f32.f16.f16.f32 "
        "{%0,%1,%2,%3}, {%4,%5,%6,%7}, {%8,%9}, {%0,%1,%2,%3};"
        : "+f"(c[0]), "+f"(c[1]), "+f"(c[2]), "+f"(c[3])
        : "r"(a[0]), "r"(a[1]), "r"(a[2]), "r"(a[3]), "r"(b0), "r"(b1));
}

// ---------------------------------------------------------------------------
// k_perm: deterministic stable class-sort ranks (grid 16, block 256)
// ---------------------------------------------------------------------------
__global__ void k_perm(const int* __restrict__ Ccls) {
    __shared__ int cls_s[KK];
    int tid = threadIdx.x;
    for (int i = tid; i < KK; i += 256) cls_s[i] = Ccls[i] & 63;
    __syncthreads();
    int i = blockIdx.x * 256 + tid;
    int ci = cls_s[i];
    int rank = 0;
    for (int j = 0; j < KK; j++) {
        int cj = cls_s[j];
        rank += (cj < ci) || (cj == ci && j < i);
    }
    g_rank[i] = rank;
    g_clsSorted[rank] = (uint8_t)ci;
}

// prep_C: fp32 -> f16, scatter rows to class-sorted positions
__global__ void prep_C(const float* __restrict__ Cmat) {
    long i = (long)blockIdx.x * 256 + threadIdx.x;      // over float4s
    int row = (int)(i >> 7), col4 = (int)(i & 127);
    float4 v = ((const float4*)Cmat)[i];
    int r = g_rank[row];
    __half2 h0 = __floats2half2_rn(v.x, v.y);
    __half2 h1 = __floats2half2_rn(v.z, v.w);
    uint2 u; u.x = *(uint32_t*)&h0; u.y = *(uint32_t*)&h1;
    ((uint2*)(g_Ch + (size_t)r * DD))[col4] = u;
}

// prep_F: l2-normalize rows of feats, f16. One warp per row.
__global__ void prep_F(const float* __restrict__ feats) {
    int row = blockIdx.x * 8 + (threadIdx.x >> 5);
    int lane = threadIdx.x & 31;
    const float4* rp = (const float4*)(feats + (size_t)row * DD);
    float4 v[4]; float ss = 0.f;
    #pragma unroll
    for (int u = 0; u < 4; u++) {
        v[u] = rp[lane + u*32];
        ss += v[u].x*v[u].x + v[u].y*v[u].y + v[u].z*v[u].z + v[u].w*v[u].w;
    }
    #pragma unroll
    for (int o = 16; o > 0; o >>= 1) ss += __shfl_xor_sync(0xffffffffu, ss, o);
    float inv = 1.0f / fmaxf(sqrtf(ss), 1e-12f);
    #pragma unroll
    for (int u = 0; u < 4; u++) {
        __half2 h0 = __floats2half2_rn(v[u].x*inv, v[u].y*inv);
        __half2 h1 = __floats2half2_rn(v[u].z*inv, v[u].w*inv);
        uint2 w; w.x = *(uint32_t*)&h0; w.y = *(uint32_t*)&h1;
        ((uint2*)(g_Fh + (size_t)row * DD))[lane + u*32] = w;
    }
}

// ---------------------------------------------------------------------------
// K1: soft-topk weights + log(P_sup)
// ---------------------------------------------------------------------------
__global__ void k_weights(const float* __restrict__ slot_prob,
                          const float* __restrict__ slot_mask) {
    int b = blockIdx.x, m = threadIdx.x;
    __shared__ float sv[MM];
    __shared__ float red[MM];
    __shared__ int   topi[3];
    __shared__ float s_mean, s_zmax, s_zsum, s_wsum, s_tmax, s_tsum;

    float mask = slot_mask[m];
    float pv = slot_prob[b*MM + m] * mask;
    sv[m] = pv;
    __syncthreads();
    if (m == 0) {
        for (int t = 0; t < 3; t++) {
            float best = -INFINITY; int bi = 0;
            for (int i = 0; i < MM; i++) if (sv[i] > best) { best = sv[i]; bi = i; }
            topi[t] = bi; sv[bi] = -INFINITY;
        }
    }
    __syncthreads();
    float keep = (m == topi[0] || m == topi[1] || m == topi[2]) ? 1.f : 0.f;
    float q = pv * keep;
    red[m] = q; __syncthreads();
    if (m == 0) { float s = 0.f; for (int i = 0; i < MM; i++) s += red[i]; s_mean = s / (float)MM; }
    __syncthreads();
    float z = (q - s_mean) * 2.0f;
    red[m] = z; __syncthreads();
    if (m == 0) { float mx = -INFINITY; for (int i = 0; i < MM; i++) mx = fmaxf(mx, red[i]); s_zmax = mx; }
    __syncthreads();
    float e = expf(z - s_zmax);
    red[m] = e; __syncthreads();
    if (m == 0) { float s = 0.f; for (int i = 0; i < MM; i++) s += red[i]; s_zsum = s; }
    __syncthreads();
    float w = (e / s_zsum) * mask;
    red[m] = w; __syncthreads();
    if (m == 0) { float s = 0.f; for (int i = 0; i < MM; i++) s += red[i]; s_wsum = s; }
    __syncthreads();
    w = w / fmaxf(s_wsum, 1e-8f);
    g_w[b*MM + m] = w;

    float t = logf(w + 1e-8f) * (1.0f/1.6f);
    red[m] = t; __syncthreads();
    if (m == 0) { float mx = -INFINITY; for (int i = 0; i < MM; i++) mx = fmaxf(mx, red[i]); s_tmax = mx; }
    __syncthreads();
    float et = expf(t - s_tmax);
    red[m] = et; __syncthreads();
    if (m == 0) { float s = 0.f; for (int i = 0; i < MM; i++) s += red[i]; s_tsum = s; }
    __syncthreads();
    float lp = t - s_tmax - logf(s_tsum);
    g_lp[b*MM + m] = fmaxf(lp, -18.420680744f);
}

// ---------------------------------------------------------------------------
// K2: single f16 HMMA GEMM + sorted-class exp-sum. One CTA per batch.
// A (64x512 f16) resident; B streamed 128 protos x 64 k, double-buffered.
// Warp layout 2x4 over 64m x 128n, warp tile 32m x 32n.
// ---------------------------------------------------------------------------
#define ASTR_B  1040u       // A row stride bytes (520 f16)
#define BSTR_B  144u        // B row stride bytes (72 f16)
#define OFF_A   0u
#define OFF_B   66560u
#define B_BUF   18432u
#define OFF_SIM 103424u     // [64][133] f32
#define OFF_SUM 137472u     // [64][4][65] f32
#define OFF_CLS 204032u     // [4096] u8
#define SMEM_EVI 208128

__device__ __forceinline__ void load_Bchunk(uint32_t base, int nt, int dc, int tid) {
    #pragma unroll
    for (int ii = 0; ii < 4; ii++) {
        int i = tid + ii*256;
        int n = i >> 3, g = i & 7;
        const __half* src = g_Ch + (size_t)(nt*128 + n)*DD + dc*64 + g*8;
        cp16(base + (uint32_t)n*BSTR_B + (uint32_t)g*16, src);
    }
}

__global__ void __launch_bounds__(256, 1)
k_evi() {
    extern __shared__ __align__(1024) char smem[];
    uint32_t smem_base = smem_to_u32(smem);
    const int tid = threadIdx.x, wid = tid >> 5, lane = tid & 31;
    const int b = blockIdx.x;
    const int wr = wid & 1, wc = wid >> 1;       // 2 row-groups x 4 col-groups

    float*   sim_s = (float*)(smem + OFF_SIM);
    float*   sums  = (float*)(smem + OFF_SUM);
    uint8_t* cls_s = (uint8_t*)(smem + OFF_CLS);

    for (int i = tid; i < 64*4*65; i += 256) sums[i] = 0.f;

    // cls bytes (one cp16 per thread)
    cp16(smem_base + OFF_CLS + (uint32_t)tid*16, g_clsSorted + tid*16);

    // resident A (64 x 512 f16, stride 520)
    #pragma unroll
    for (int ii = 0; ii < 16; ii++) {
        int i = tid + ii*256;
        int r = i >> 6, g = i & 63;
        const __half* src = g_Fh + ((size_t)b*MM + r)*DD + g*8;
        cp16(smem_base + OFF_A + (uint32_t)r*ASTR_B + (uint32_t)g*16, src);
    }
    cp_commit();

    load_Bchunk(smem_base + OFF_B, 0, 0, tid);
    cp_commit();

    const uint32_t aBase = smem_base + OFF_A
        + (uint32_t)(wr*32 + (lane & 15))*ASTR_B + (uint32_t)(lane >> 4)*16;
    const uint32_t bLane = (uint32_t)((lane & 7) + ((lane >> 4) << 3))*BSTR_B
        + (uint32_t)((lane >> 3) & 1)*16;

    const int r_lse = tid >> 2, qg = tid & 3;

    float acc[2][4][4];

    for (int q = 0; q < 256; ++q) {
        const int nt = q >> 3, dc = q & 7, buf = q & 1;
        if (q + 1 < 256) {
            load_Bchunk(smem_base + OFF_B + (uint32_t)((q+1) & 1)*B_BUF, (q+1) >> 3, (q+1) & 7, tid);
            cp_commit();
            cp_wait1();
        } else {
            cp_wait0();
        }
        __syncthreads();

        if (dc == 0) {
            #pragma unroll
            for (int s = 0; s < 2; s++)
                #pragma unroll
                for (int nf = 0; nf < 4; nf++)
                    #pragma unroll
                    for (int j = 0; j < 4; j++) acc[s][nf][j] = 0.f;
        }

        const uint32_t bBuf = smem_base + OFF_B + (uint32_t)buf*B_BUF + (uint32_t)(wc*32)*BSTR_B;
        #pragma unroll
        for (int ks = 0; ks < 4; ++ks) {
            uint32_t a0[4], a1[4];
            uint32_t kb = (uint32_t)(dc*64 + ks*16)*2;
            ldm_x4(a0, aBase + kb);
            ldm_x4(a1, aBase + 16*ASTR_B + kb);
            uint32_t b01[4], b23[4];
            uint32_t bAddr = bBuf + bLane + (uint32_t)ks*32;
            ldm_x4(b01, bAddr);
            ldm_x4(b23, bAddr + 16*BSTR_B);
            mma16816(acc[0][0], a0, b01[0], b01[1]);
            mma16816(acc[0][1], a0, b01[2], b01[3]);
            mma16816(acc[0][2], a0, b23[0], b23[1]);
            mma16816(acc[0][3], a0, b23[2], b23[3]);
            mma16816(acc[1][0], a1, b01[0], b01[1]);
            mma16816(acc[1][1], a1, b01[2], b01[3]);
            mma16816(acc[1][2], a1, b23[0], b23[1]);
            mma16816(acc[1][3], a1, b23[2], b23[3]);
        }

        if (dc == 7) {
            // write sim tile (rows 0..63, cols 0..127)
            int r0 = wr*32 + (lane >> 2);
            int c0 = wc*32 + (lane & 3)*2;
            #pragma unroll
            for (int s = 0; s < 2; s++) {
                #pragma unroll
                for (int nf = 0; nf < 4; nf++) {
                    int rr = r0 + s*16, cc = c0 + nf*8;
                    sim_s[rr*133 + cc]       = acc[s][nf][0];
                    sim_s[rr*133 + cc + 1]   = acc[s][nf][1];
                    sim_s[(rr+8)*133 + cc]     = acc[s][nf][2];
                    sim_s[(rr+8)*133 + cc + 1] = acc[s][nf][3];
                }
            }
            __syncthreads();
            // sorted-class run sum into private qg slice (tau=0.5 -> exp(2s))
            const uint8_t* clsrun = cls_s + nt*128 + qg*32;
            float* sumrow = sums + (r_lse*4 + qg)*65;
            const float* simr = sim_s + r_lse*133 + qg*32;
            float s = 0.f;
            int cur = (int)clsrun[0];
            #pragma unroll 8
            for (int p = 0; p < 32; ++p) {
                int c = (int)clsrun[p];
                float e = __expf(2.0f * simr[p]);
                if (c != cur) { sumrow[cur] += s; s = 0.f; cur = c; }
                s += e;
            }
            sumrow[cur] += s;
        }
    }
    __syncthreads();

    // evi = tau * log(sum of 4 slices)
    {
        float* dst = g_evi + ((size_t)b*MM + r_lse)*CC;
        #pragma unroll
        for (int j = 0; j < 16; ++j) {
            int c = qg*16 + j;
            float v = sums[(r_lse*4 + 0)*65 + c] + sums[(r_lse*4 + 1)*65 + c]
                    + sums[(r_lse*4 + 2)*65 + c] + sums[(r_lse*4 + 3)*65 + c];
            dst[c] = 0.5f * logf(fmaxf(v, 1e-8f));
        }
    }
}

// ---------------------------------------------------------------------------
// K3: epilogue per batch (top1, cosines vs top1 slots, support LSE)
// ---------------------------------------------------------------------------
__global__ void __launch_bounds__(256, 1)
k_out(const float* __restrict__ S_slots,
      const float* __restrict__ alpha,
      float* __restrict__ out) {
    extern __shared__ float sm[];
    float* s_s   = sm;                        // [512][68]
    float* tf_s  = s_s  + DD*SSTRIDE;         // [256][68]; reused as sup_s
    float* evi_s = tf_s + 256*SSTRIDE;        // [64*64]
    float* w_s   = evi_s + MM*CC;
    float* lp_s  = w_s + MM;
    float* t1v   = lp_s + MM;
    int*   t1i   = (int*)(t1v + MM);

    int b = blockIdx.x, tid = threadIdx.x;
    int wid = tid >> 5, lane = tid & 31;

    for (int i = tid; i < MM*CC; i += 256) evi_s[i] = g_evi[(size_t)b*MM*CC + i];
    if (tid < MM) { w_s[tid] = g_w[b*MM + tid]; lp_s[tid] = g_lp[b*MM + tid]; }

    const float* sb = S_slots + (size_t)b*MM*DD;
    for (int rr = 0; rr < 8; rr++) {
        int r = wid*8 + rr;
        const float4* rp = (const float4*)(sb + r*DD);
        float4 v[4]; float ss = 0.f;
        #pragma unroll
        for (int u = 0; u < 4; u++) {
            v[u] = rp[u*32 + lane];
            ss += v[u].x*v[u].x + v[u].y*v[u].y + v[u].z*v[u].z + v[u].w*v[u].w;
        }
        #pragma unroll
        for (int o = 16; o > 0; o >>= 1) ss += __shfl_xor_sync(0xffffffffu, ss, o);
        float inv = 1.0f / fmaxf(sqrtf(ss), 1e-12f);
        #pragma unroll
        for (int u = 0; u < 4; u++) {
            int d0 = u*128 + lane*4;
            s_s[(d0+0)*SSTRIDE + r] = v[u].x * inv;
            s_s[(d0+1)*SSTRIDE + r] = v[u].y * inv;
            s_s[(d0+2)*SSTRIDE + r] = v[u].z * inv;
            s_s[(d0+3)*SSTRIDE + r] = v[u].w * inv;
        }
    }
    __syncthreads();

    if (tid < CC) {
        int c = tid;
        float best = -INFINITY; int bi = 0;
        for (int m = 0; m < MM; m++) {
            float sc = evi_s[m*CC + c] * w_s[m];
            if (sc > best) { best = sc; bi = m; }
        }
        t1v[c] = best; t1i[c] = bi;
    }
    __syncthreads();

    int tr = tid >> 4, tc = tid & 15;
    int gc = tid >> 2, gq = tid & 3;
    float acc[4][4] = {};
    #pragma unroll 1
    for (int h = 0; h < 2; h++) {
        __syncthreads();
        {
            int src = t1i[gc];
            for (int u = 0; u < 64; u++) {
                int k = gq*64 + u;
                tf_s[k*SSTRIDE + gc] = s_s[(h*256 + k)*SSTRIDE + src];
            }
        }
        __syncthreads();
        const float* fp = s_s  + h*256*SSTRIDE + tr*4;
        const float* gp = tf_s + tc*4;
        #pragma unroll 4
        for (int k = 0; k < 256; k++) {
            float4 fv = *(const float4*)(fp + k*SSTRIDE);
            float4 gv = *(const float4*)(gp + k*SSTRIDE);
            acc[0][0] = fmaf(fv.x, gv.x, acc[0][0]);
            acc[0][1] = fmaf(fv.x, gv.y, acc[0][1]);
            acc[0][2] = fmaf(fv.x, gv.z, acc[0][2]);
            acc[0][3] = fmaf(fv.x, gv.w, acc[0][3]);
            acc[1][0] = fmaf(fv.y, gv.x, acc[1][0]);
            acc[1][1] = fmaf(fv.y, gv.y, acc[1][1]);
            acc[1][2] = fmaf(fv.y, gv.z, acc[1][2]);
            acc[1][3] = fmaf(fv.y, gv.w, acc[1][3]);
            acc[2][0] = fmaf(fv.z, gv.x, acc[2][0]);
            acc[2][1] = fmaf(fv.z, gv.y, acc[2][1]);
            acc[2][2] = fmaf(fv.z, gv.z, acc[2][2]);
            acc[2][3] = fmaf(fv.z, gv.w, acc[2][3]);
            acc[3][0] = fmaf(fv.w, gv.x, acc[3][0]);
            acc[3][1] = fmaf(fv.w, gv.y, acc[3][1]);
            acc[3][2] = fmaf(fv.w, gv.z, acc[3][2]);
            acc[3][3] = fmaf(fv.w, gv.w, acc[3][3]);
        }
    }
    __syncthreads();
    float* sup_s = tf_s;
    #pragma unroll
    for (int i = 0; i < 4; i++) {
        #pragma unroll
        for (int j = 0; j < 4; j++) {
            int m = tr*4 + i, c = tc*4 + j;
            float cosv = fmaxf(acc[i][j], 0.f);
            float sr = evi_s[m*CC + c] + lp_s[m] - cosv;
            if (m == t1i[c]) sr = -10000.0f;
            sup_s[m*CC + c] = sr;
        }
    }
    __syncthreads();
    if (tid < CC) {
        int c = tid;
        float mx = -INFINITY;
        for (int m = 0; m < MM; m++) mx = fmaxf(mx, sup_s[m*CC + c]);
        float sum = 0.f;
        for (int m = 0; m < MM; m++) sum += expf(sup_s[m*CC + c] - mx);
        float sval = mx + logf(sum);
        out[b*CC + c] = alpha[0] * (t1v[c] + 0.4f * sval);
    }
}

// ---------------------------------------------------------------------------
extern "C" void kernel_launch(void* const* d_in, const int* in_sizes, int n_in,
                              void* d_out, int out_size) {
    const float* feats     = (const float*)d_in[0];
    const float* slot_prob = (const float*)d_in[1];
    const float* slot_mask = (const float*)d_in[2];
    const float* S_slots   = (const float*)d_in[3];
    const float* Cmat      = (const float*)d_in[4];
    const int*   Ccls      = (const int*)d_in[5];
    const float* alpha     = (const float*)d_in[6];
    float* out = (float*)d_out;

    const int smem3 = (DD*SSTRIDE + 256*SSTRIDE + MM*CC + 3*MM) * 4 + MM * 4;

    cudaFuncSetAttribute(k_evi, cudaFuncAttributeMaxDynamicSharedMemorySize, SMEM_EVI);
    cudaFuncSetAttribute(k_out, cudaFuncAttributeMaxDynamicSharedMemorySize, smem3);

    k_weights<<<BB, MM>>>(slot_prob, slot_mask);
    k_perm<<<KK/256, 256>>>(Ccls);
    prep_C<<<KK*DD/1024, 256>>>(Cmat);
    prep_F<<<BB*MM/8, 256>>>(feats);
    k_evi<<<BB, 256, SMEM_EVI>>>();
    k_out<<<BB, 256, smem3>>>(S_slots, alpha, out);
}

// round 5
// speedup vs baseline: 7.9999x; 1.1864x over previous
#include <cuda_runtime.h>
#include <cuda_fp16.h>
#include <math.h>
#include <stdint.h>

#define BB 128
#define MM 64
#define DD 512
#define KK 4096
#define CC 64
#define SSTRIDE 68

// ---------------------------------------------------------------------------
// scratch (__device__ globals per allocation-free rule)
// ---------------------------------------------------------------------------
__device__ __align__(16) __half g_Fh[BB*MM*DD];   // normalized feats, f16
__device__ __align__(16) __half g_Ch[KK*DD];      // C, f16, class-sorted rows
__device__ int     g_rank[KK];
__device__ uint8_t g_clsSorted[KK];
__device__ float   g_evi[BB*MM*CC];
__device__ float   g_w[BB*MM];
__device__ float   g_lp[BB*MM];

// ---------------------------------------------------------------------------
__device__ __forceinline__ uint32_t smem_to_u32(const void* p) {
    uint32_t a;
    asm("{ .reg .u64 t; cvta.to.shared.u64 t, %1; cvt.u32.u64 %0, t; }" : "=r"(a) : "l"(p));
    return a;
}
__device__ __forceinline__ void cp16(uint32_t dst, const void* src) {
    asm volatile("cp.async.cg.shared.global [%0], [%1], 16;" :: "r"(dst), "l"(src));
}
__device__ __forceinline__ void cp_commit() { asm volatile("cp.async.commit_group;" ::: "memory"); }
__device__ __forceinline__ void cp_wait0()  { asm volatile("cp.async.wait_group 0;" ::: "memory"); }
__device__ __forceinline__ void cp_wait1()  { asm volatile("cp.async.wait_group 1;" ::: "memory"); }

__device__ __forceinline__ void ldm_x4(uint32_t r[4], uint32_t addr) {
    asm volatile("ldmatrix.sync.aligned.m8n8.x4.shared.b16 {%0,%1,%2,%3}, [%4];"
        : "=r"(r[0]), "=r"(r[1]), "=r"(r[2]), "=r"(r[3]) : "r"(addr));
}
__device__ __forceinline__ void mma16816(float* c, const uint32_t* a, uint32_t b0, uint32_t b1) {
    asm volatile(
        "mma.sync.aligned.m16n8k16.row.col.f32.f16.f16.f32 "
        "{%0,%1,%2,%3}, {%4,%5,%6,%7}, {%8,%9}, {%0,%1,%2,%3};"
        : "+f"(c[0]), "+f"(c[1]), "+f"(c[2]), "+f"(c[3])
        : "r"(a[0]), "r"(a[1]), "r"(a[2]), "r"(a[3]), "r"(b0), "r"(b1));
}

// ---------------------------------------------------------------------------
// k_perm: deterministic stable class-sort ranks (grid 16, block 256)
// ---------------------------------------------------------------------------
__global__ void k_perm(const int* __restrict__ Ccls) {
    __shared__ int cls_s[KK];
    int tid = threadIdx.x;
    for (int i = tid; i < KK; i += 256) cls_s[i] = Ccls[i] & 63;
    __syncthreads();
    int i = blockIdx.x * 256 + tid;
    int ci = cls_s[i];
    int rank = 0;
    for (int j = 0; j < KK; j++) {
        int cj = cls_s[j];
        rank += (cj < ci) || (cj == ci && j < i);
    }
    g_rank[i] = rank;
    g_clsSorted[rank] = (uint8_t)ci;
}

// prep_C: fp32 -> f16, scatter rows to class-sorted positions
__global__ void prep_C(const float* __restrict__ Cmat) {
    long i = (long)blockIdx.x * 256 + threadIdx.x;      // over float4s
    int row = (int)(i >> 7), col4 = (int)(i & 127);
    float4 v = ((const float4*)Cmat)[i];
    int r = g_rank[row];
    __half2 h0 = __floats2half2_rn(v.x, v.y);
    __half2 h1 = __floats2half2_rn(v.z, v.w);
    uint2 u; u.x = *(uint32_t*)&h0; u.y = *(uint32_t*)&h1;
    ((uint2*)(g_Ch + (size_t)r * DD))[col4] = u;
}

// prep_F: l2-normalize rows of feats, f16. One warp per row.
__global__ void prep_F(const float* __restrict__ feats) {
    int row = blockIdx.x * 8 + (threadIdx.x >> 5);
    int lane = threadIdx.x & 31;
    const float4* rp = (const float4*)(feats + (size_t)row * DD);
    float4 v[4]; float ss = 0.f;
    #pragma unroll
    for (int u = 0; u < 4; u++) {
        v[u] = rp[lane + u*32];
        ss += v[u].x*v[u].x + v[u].y*v[u].y + v[u].z*v[u].z + v[u].w*v[u].w;
    }
    #pragma unroll
    for (int o = 16; o > 0; o >>= 1) ss += __shfl_xor_sync(0xffffffffu, ss, o);
    float inv = 1.0f / fmaxf(sqrtf(ss), 1e-12f);
    #pragma unroll
    for (int u = 0; u < 4; u++) {
        __half2 h0 = __floats2half2_rn(v[u].x*inv, v[u].y*inv);
        __half2 h1 = __floats2half2_rn(v[u].z*inv, v[u].w*inv);
        uint2 w; w.x = *(uint32_t*)&h0; w.y = *(uint32_t*)&h1;
        ((uint2*)(g_Fh + (size_t)row * DD))[lane + u*32] = w;
    }
}

// ---------------------------------------------------------------------------
// K1: soft-topk weights + log(P_sup)
// ---------------------------------------------------------------------------
__global__ void k_weights(const float* __restrict__ slot_prob,
                          const float* __restrict__ slot_mask) {
    int b = blockIdx.x, m = threadIdx.x;
    __shared__ float sv[MM];
    __shared__ float red[MM];
    __shared__ int   topi[3];
    __shared__ float s_mean, s_zmax, s_zsum, s_wsum, s_tmax, s_tsum;

    float mask = slot_mask[m];
    float pv = slot_prob[b*MM + m] * mask;
    sv[m] = pv;
    __syncthreads();
    if (m == 0) {
        for (int t = 0; t < 3; t++) {
            float best = -INFINITY; int bi = 0;
            for (int i = 0; i < MM; i++) if (sv[i] > best) { best = sv[i]; bi = i; }
            topi[t] = bi; sv[bi] = -INFINITY;
        }
    }
    __syncthreads();
    float keep = (m == topi[0] || m == topi[1] || m == topi[2]) ? 1.f : 0.f;
    float q = pv * keep;
    red[m] = q; __syncthreads();
    if (m == 0) { float s = 0.f; for (int i = 0; i < MM; i++) s += red[i]; s_mean = s / (float)MM; }
    __syncthreads();
    float z = (q - s_mean) * 2.0f;
    red[m] = z; __syncthreads();
    if (m == 0) { float mx = -INFINITY; for (int i = 0; i < MM; i++) mx = fmaxf(mx, red[i]); s_zmax = mx; }
    __syncthreads();
    float e = expf(z - s_zmax);
    red[m] = e; __syncthreads();
    if (m == 0) { float s = 0.f; for (int i = 0; i < MM; i++) s += red[i]; s_zsum = s; }
    __syncthreads();
    float w = (e / s_zsum) * mask;
    red[m] = w; __syncthreads();
    if (m == 0) { float s = 0.f; for (int i = 0; i < MM; i++) s += red[i]; s_wsum = s; }
    __syncthreads();
    w = w / fmaxf(s_wsum, 1e-8f);
    g_w[b*MM + m] = w;

    float t = logf(w + 1e-8f) * (1.0f/1.6f);
    red[m] = t; __syncthreads();
    if (m == 0) { float mx = -INFINITY; for (int i = 0; i < MM; i++) mx = fmaxf(mx, red[i]); s_tmax = mx; }
    __syncthreads();
    float et = expf(t - s_tmax);
    red[m] = et; __syncthreads();
    if (m == 0) { float s = 0.f; for (int i = 0; i < MM; i++) s += red[i]; s_tsum = s; }
    __syncthreads();
    float lp = t - s_tmax - logf(s_tsum);
    g_lp[b*MM + m] = fmaxf(lp, -18.420680744f);
}

// ---------------------------------------------------------------------------
// K2: f16 HMMA GEMM + in-register class exp-sum. One CTA per batch.
// A (64x512 f16) resident; B streamed 256 protos x 64 k, 3-stage cp.async.
// Warps 2(m) x 4(n); warp tile 32m x 64n (= one sorted class per warp slab).
// ---------------------------------------------------------------------------
#define ASTR_B  1040u       // A row stride bytes (520 f16)
#define BSTR_B  144u        // B row stride bytes (72 f16)
#define OFF_A   0u
#define OFF_B   66560u
#define B_BUF   36864u      // 256 rows x 144 B
#define OFF_PART 177152u    // [64][5] f32
#define OFF_CLS  178432u    // [4096] u8
#define SMEM_EVI 182528

// chunk q: nt = q>>3 (256-proto tile), dc = q&7 (64-k chunk)
__device__ __forceinline__ void load_Bchunk(uint32_t base, int q, int tid) {
    const int nt = q >> 3, dc = q & 7;
    const __half* src0 = g_Ch + (size_t)(nt*256)*DD + dc*64;
    #pragma unroll
    for (int ii = 0; ii < 8; ii++) {
        int i = tid + ii*256;
        int n = i >> 3, g = i & 7;
        cp16(base + (uint32_t)n*BSTR_B + (uint32_t)g*16, src0 + (size_t)n*DD + g*8);
    }
}

__global__ void __launch_bounds__(256, 1)
k_evi() {
    extern __shared__ __align__(1024) char smem[];
    uint32_t smem_base = smem_to_u32(smem);
    const int tid = threadIdx.x, wid = tid >> 5, lane = tid & 31;
    const int b = blockIdx.x;
    const int wr = wid & 1, wc = wid >> 1;     // 2 row-groups x 4 col-groups

    float*   part  = (float*)(smem + OFF_PART);   // [64][5]
    uint8_t* cls_s = (uint8_t*)(smem + OFF_CLS);

    // cls bytes
    cp16(smem_base + OFF_CLS + (uint32_t)tid*16, g_clsSorted + tid*16);

    // resident A (64 x 512 f16, stride 520)
    #pragma unroll
    for (int ii = 0; ii < 16; ii++) {
        int i = tid + ii*256;
        int r = i >> 6, g = i & 63;
        const __half* src = g_Fh + ((size_t)b*MM + r)*DD + g*8;
        cp16(smem_base + OFF_A + (uint32_t)r*ASTR_B + (uint32_t)g*16, src);
    }
    load_Bchunk(smem_base + OFF_B, 0, tid);
    cp_commit();
    load_Bchunk(smem_base + OFF_B + B_BUF, 1, tid);
    cp_commit();

    const uint32_t aBase = smem_base + OFF_A
        + (uint32_t)(wr*32 + (lane & 15))*ASTR_B + (uint32_t)(lane >> 4)*16;
    const uint32_t bLane = (uint32_t)((lane & 7) + ((lane >> 4) << 3))*BSTR_B
        + (uint32_t)((lane >> 3) & 1)*16;

    float acc[2][8][4];
    int bufsel = 0;     // q % 3

    for (int q = 0; q < 128; ++q) {
        const int nt = q >> 3, dc = q & 7;
        if (q < 126) cp_wait1(); else cp_wait0();
        __syncthreads();

        if (q + 2 < 128) {
            int nb = bufsel + 2; if (nb >= 3) nb -= 3;
            load_Bchunk(smem_base + OFF_B + (uint32_t)nb*B_BUF, q + 2, tid);
            cp_commit();
        }

        if (dc == 0) {
            #pragma unroll
            for (int m = 0; m < 2; m++)
                #pragma unroll
                for (int nf = 0; nf < 8; nf++)
                    #pragma unroll
                    for (int j = 0; j < 4; j++) acc[m][nf][j] = 0.f;
        }

        const uint32_t bBuf = smem_base + OFF_B + (uint32_t)bufsel*B_BUF
                            + (uint32_t)(wc*64)*BSTR_B + bLane;
        #pragma unroll
        for (int ks = 0; ks < 4; ++ks) {
            uint32_t a0[4], a1[4];
            uint32_t kb = (uint32_t)(dc*64 + ks*16)*2;
            ldm_x4(a0, aBase + kb);
            ldm_x4(a1, aBase + 16*ASTR_B + kb);
            uint32_t bf0[4], bf1[4], bf2[4], bf3[4];
            uint32_t bAddr = bBuf + (uint32_t)ks*32;
            ldm_x4(bf0, bAddr);
            ldm_x4(bf1, bAddr + 16*BSTR_B);
            ldm_x4(bf2, bAddr + 32*BSTR_B);
            ldm_x4(bf3, bAddr + 48*BSTR_B);
            mma16816(acc[0][0], a0, bf0[0], bf0[1]);
            mma16816(acc[0][1], a0, bf0[2], bf0[3]);
            mma16816(acc[0][2], a0, bf1[0], bf1[1]);
            mma16816(acc[0][3], a0, bf1[2], bf1[3]);
            mma16816(acc[0][4], a0, bf2[0], bf2[1]);
            mma16816(acc[0][5], a0, bf2[2], bf2[3]);
            mma16816(acc[0][6], a0, bf3[0], bf3[1]);
            mma16816(acc[0][7], a0, bf3[2], bf3[3]);
            mma16816(acc[1][0], a1, bf0[0], bf0[1]);
            mma16816(acc[1][1], a1, bf0[2], bf0[3]);
            mma16816(acc[1][2], a1, bf1[0], bf1[1]);
            mma16816(acc[1][3], a1, bf1[2], bf1[3]);
            mma16816(acc[1][4], a1, bf2[0], bf2[1]);
            mma16816(acc[1][5], a1, bf2[2], bf2[3]);
            mma16816(acc[1][6], a1, bf3[0], bf3[1]);
            mma16816(acc[1][7], a1, bf3[2], bf3[3]);
        }

        if (dc == 7) {
            // in-register exp + row reduce over this warp's 64 cols (one class)
            #pragma unroll
            for (int m = 0; m < 2; m++) {
                #pragma unroll
                for (int h = 0; h < 2; h++) {
                    float s = 0.f;
                    #pragma unroll
                    for (int nf = 0; nf < 8; nf++) {
                        s += __expf(2.0f * acc[m][nf][h*2 + 0]);
                        s += __expf(2.0f * acc[m][nf][h*2 + 1]);
                    }
                    s += __shfl_xor_sync(0xffffffffu, s, 1);
                    s += __shfl_xor_sync(0xffffffffu, s, 2);
                    if ((lane & 3) == 0) {
                        int row = wr*32 + m*16 + h*8 + (lane >> 2);
                        part[row*5 + wc] = s;
                    }
                }
            }
            __syncthreads();
            if (tid < MM) {
                float* dst = g_evi + ((size_t)b*MM + tid)*CC;
                #pragma unroll
                for (int j = 0; j < 4; ++j) {
                    int c = (int)cls_s[nt*256 + j*64];
                    dst[c] = 0.5f * logf(fmaxf(part[tid*5 + j], 1e-8f));
                }
            }
        }
        if (++bufsel == 3) bufsel = 0;
    }
}

// ---------------------------------------------------------------------------
// K3: epilogue per batch (top1, cosines vs top1 slots, support LSE)
// ---------------------------------------------------------------------------
__global__ void __launch_bounds__(256, 1)
k_out(const float* __restrict__ S_slots,
      const float* __restrict__ alpha,
      float* __restrict__ out) {
    extern __shared__ float sm[];
    float* s_s   = sm;                        // [512][68]
    float* tf_s  = s_s  + DD*SSTRIDE;         // [256][68]; reused as sup_s
    float* evi_s = tf_s + 256*SSTRIDE;        // [64*64]
    float* w_s   = evi_s + MM*CC;
    float* lp_s  = w_s + MM;
    float* t1v   = lp_s + MM;
    int*   t1i   = (int*)(t1v + MM);

    int b = blockIdx.x, tid = threadIdx.x;
    int wid = tid >> 5, lane = tid & 31;

    for (int i = tid; i < MM*CC; i += 256) evi_s[i] = g_evi[(size_t)b*MM*CC + i];
    if (tid < MM) { w_s[tid] = g_w[b*MM + tid]; lp_s[tid] = g_lp[b*MM + tid]; }

    const float* sb = S_slots + (size_t)b*MM*DD;
    for (int rr = 0; rr < 8; rr++) {
        int r = wid*8 + rr;
        const float4* rp = (const float4*)(sb + r*DD);
        float4 v[4]; float ss = 0.f;
        #pragma unroll
        for (int u = 0; u < 4; u++) {
            v[u] = rp[u*32 + lane];
            ss += v[u].x*v[u].x + v[u].y*v[u].y + v[u].z*v[u].z + v[u].w*v[u].w;
        }
        #pragma unroll
        for (int o = 16; o > 0; o >>= 1) ss += __shfl_xor_sync(0xffffffffu, ss, o);
        float inv = 1.0f / fmaxf(sqrtf(ss), 1e-12f);
        #pragma unroll
        for (int u = 0; u < 4; u++) {
            int d0 = u*128 + lane*4;
            s_s[(d0+0)*SSTRIDE + r] = v[u].x * inv;
            s_s[(d0+1)*SSTRIDE + r] = v[u].y * inv;
            s_s[(d0+2)*SSTRIDE + r] = v[u].z * inv;
            s_s[(d0+3)*SSTRIDE + r] = v[u].w * inv;
        }
    }
    __syncthreads();

    if (tid < CC) {
        int c = tid;
        float best = -INFINITY; int bi = 0;
        for (int m = 0; m < MM; m++) {
            float sc = evi_s[m*CC + c] * w_s[m];
            if (sc > best) { best = sc; bi = m; }
        }
        t1v[c] = best; t1i[c] = bi;
    }
    __syncthreads();

    int tr = tid >> 4, tc = tid & 15;
    int gc = tid >> 2, gq = tid & 3;
    float acc[4][4] = {};
    #pragma unroll 1
    for (int h = 0; h < 2; h++) {
        __syncthreads();
        {
            int src = t1i[gc];
            for (int u = 0; u < 64; u++) {
                int k = gq*64 + u;
                tf_s[k*SSTRIDE + gc] = s_s[(h*256 + k)*SSTRIDE + src];
            }
        }
        __syncthreads();
        const float* fp = s_s  + h*256*SSTRIDE + tr*4;
        const float* gp = tf_s + tc*4;
        #pragma unroll 4
        for (int k = 0; k < 256; k++) {
            float4 fv = *(const float4*)(fp + k*SSTRIDE);
            float4 gv = *(const float4*)(gp + k*SSTRIDE);
            acc[0][0] = fmaf(fv.x, gv.x, acc[0][0]);
            acc[0][1] = fmaf(fv.x, gv.y, acc[0][1]);
            acc[0][2] = fmaf(fv.x, gv.z, acc[0][2]);
            acc[0][3] = fmaf(fv.x, gv.w, acc[0][3]);
            acc[1][0] = fmaf(fv.y, gv.x, acc[1][0]);
            acc[1][1] = fmaf(fv.y, gv.y, acc[1][1]);
            acc[1][2] = fmaf(fv.y, gv.z, acc[1][2]);
            acc[1][3] = fmaf(fv.y, gv.w, acc[1][3]);
            acc[2][0] = fmaf(fv.z, gv.x, acc[2][0]);
            acc[2][1] = fmaf(fv.z, gv.y, acc[2][1]);
            acc[2][2] = fmaf(fv.z, gv.z, acc[2][2]);
            acc[2][3] = fmaf(fv.z, gv.w, acc[2][3]);
            acc[3][0] = fmaf(fv.w, gv.x, acc[3][0]);
            acc[3][1] = fmaf(fv.w, gv.y, acc[3][1]);
            acc[3][2] = fmaf(fv.w, gv.z, acc[3][2]);
            acc[3][3] = fmaf(fv.w, gv.w, acc[3][3]);
        }
    }
    __syncthreads();
    float* sup_s = tf_s;
    #pragma unroll
    for (int i = 0; i < 4; i++) {
        #pragma unroll
        for (int j = 0; j < 4; j++) {
            int m = tr*4 + i, c = tc*4 + j;
            float cosv = fmaxf(acc[i][j], 0.f);
            float sr = evi_s[m*CC + c] + lp_s[m] - cosv;
            if (m == t1i[c]) sr = -10000.0f;
            sup_s[m*CC + c] = sr;
        }
    }
    __syncthreads();
    if (tid < CC) {
        int c = tid;
        float mx = -INFINITY;
        for (int m = 0; m < MM; m++) mx = fmaxf(mx, sup_s[m*CC + c]);
        float sum = 0.f;
        for (int m = 0; m < MM; m++) sum += expf(sup_s[m*CC + c] - mx);
        float sval = mx + logf(sum);
        out[b*CC + c] = alpha[0] * (t1v[c] + 0.4f * sval);
    }
}

// ---------------------------------------------------------------------------
extern "C" void kernel_launch(void* const* d_in, const int* in_sizes, int n_in,
                              void* d_out, int out_size) {
    const float* feats     = (const float*)d_in[0];
    const float* slot_prob = (const float*)d_in[1];
    const float* slot_mask = (const float*)d_in[2];
    const float* S_slots   = (const float*)d_in[3];
    const float* Cmat      = (const float*)d_in[4];
    const int*   Ccls      = (const int*)d_in[5];
    const float* alpha     = (const float*)d_in[6];
    float* out = (float*)d_out;

    const int smem3 = (DD*SSTRIDE + 256*SSTRIDE + MM*CC + 3*MM) * 4 + MM * 4;

    cudaFuncSetAttribute(k_evi, cudaFuncAttributeMaxDynamicSharedMemorySize, SMEM_EVI);
    cudaFuncSetAttribute(k_out, cudaFuncAttributeMaxDynamicSharedMemorySize, smem3);

    k_weights<<<BB, MM>>>(slot_prob, slot_mask);
    k_perm<<<KK/256, 256>>>(Ccls);
    prep_C<<<KK*DD/1024, 256>>>(Cmat);
    prep_F<<<BB*MM/8, 256>>>(feats);
    k_evi<<<BB, 256, SMEM_EVI>>>();
    k_out<<<BB, 256, smem3>>>(S_slots, alpha, out);
}

// round 6
// speedup vs baseline: 8.7101x; 1.0888x over previous
#include <cuda_runtime.h>
#include <cuda_fp16.h>
#include <math.h>
#include <stdint.h>

#define BB 128
#define MM 64
#define DD 512
#define KK 4096
#define CC 64
#define SSTRIDE 68

// ---------------------------------------------------------------------------
// scratch (__device__ globals per allocation-free rule)
// ---------------------------------------------------------------------------
__device__ __align__(16) __half g_Fh[BB*MM*DD];   // normalized feats, f16
__device__ __align__(16) __half g_Ch[KK*DD];      // C, f16, class-sorted rows
__device__ int     g_rank[KK];
__device__ uint8_t g_clsSorted[KK];
__device__ float   g_evi[BB*MM*CC];
__device__ float   g_w[BB*MM];
__device__ float   g_lp[BB*MM];

// ---------------------------------------------------------------------------
__device__ __forceinline__ uint32_t smem_to_u32(const void* p) {
    uint32_t a;
    asm("{ .reg .u64 t; cvta.to.shared.u64 t, %1; cvt.u32.u64 %0, t; }" : "=r"(a) : "l"(p));
    return a;
}
__device__ __forceinline__ void cp16(uint32_t dst, const void* src) {
    asm volatile("cp.async.cg.shared.global [%0], [%1], 16;" :: "r"(dst), "l"(src));
}
__device__ __forceinline__ void cp_commit() { asm volatile("cp.async.commit_group;" ::: "memory"); }
__device__ __forceinline__ void cp_wait0()  { asm volatile("cp.async.wait_group 0;" ::: "memory"); }
__device__ __forceinline__ void cp_wait1()  { asm volatile("cp.async.wait_group 1;" ::: "memory"); }

__device__ __forceinline__ void ldm_x4(uint32_t r[4], uint32_t addr) {
    asm volatile("ldmatrix.sync.aligned.m8n8.x4.shared.b16 {%0,%1,%2,%3}, [%4];"
        : "=r"(r[0]), "=r"(r[1]), "=r"(r[2]), "=r"(r[3]) : "r"(addr));
}
__device__ __forceinline__ void mma16816(float* c, const uint32_t* a, uint32_t b0, uint32_t b1) {
    asm volatile(
        "mma.sync.aligned.m16n8k16.row.col.f32.f16.f16.f32 "
        "{%0,%1,%2,%3}, {%4,%5,%6,%7}, {%8,%9}, {%0,%1,%2,%3};"
        : "+f"(c[0]), "+f"(c[1]), "+f"(c[2]), "+f"(c[3])
        : "r"(a[0]), "r"(a[1]), "r"(a[2]), "r"(a[3]), "r"(b0), "r"(b1));
}

// ---------------------------------------------------------------------------
// k_perm: deterministic stable class-sort ranks (grid 16, block 256)
// ---------------------------------------------------------------------------
__global__ void k_perm(const int* __restrict__ Ccls) {
    __shared__ int cls_s[KK];
    int tid = threadIdx.x;
    for (int i = tid; i < KK; i += 256) cls_s[i] = Ccls[i] & 63;
    __syncthreads();
    int i = blockIdx.x * 256 + tid;
    int ci = cls_s[i];
    int rank = 0;
    for (int j = 0; j < KK; j++) {
        int cj = cls_s[j];
        rank += (cj < ci) || (cj == ci && j < i);
    }
    g_rank[i] = rank;
    g_clsSorted[rank] = (uint8_t)ci;
}

// prep_C: fp32 -> f16, scatter rows to class-sorted positions
__global__ void prep_C(const float* __restrict__ Cmat) {
    long i = (long)blockIdx.x * 256 + threadIdx.x;      // over float4s
    int row = (int)(i >> 7), col4 = (int)(i & 127);
    float4 v = ((const float4*)Cmat)[i];
    int r = g_rank[row];
    __half2 h0 = __floats2half2_rn(v.x, v.y);
    __half2 h1 = __floats2half2_rn(v.z, v.w);
    uint2 u; u.x = *(uint32_t*)&h0; u.y = *(uint32_t*)&h1;
    ((uint2*)(g_Ch + (size_t)r * DD))[col4] = u;
}

// prep_F: l2-normalize rows of feats, f16. One warp per row.
__global__ void prep_F(const float* __restrict__ feats) {
    int row = blockIdx.x * 8 + (threadIdx.x >> 5);
    int lane = threadIdx.x & 31;
    const float4* rp = (const float4*)(feats + (size_t)row * DD);
    float4 v[4]; float ss = 0.f;
    #pragma unroll
    for (int u = 0; u < 4; u++) {
        v[u] = rp[lane + u*32];
        ss += v[u].x*v[u].x + v[u].y*v[u].y + v[u].z*v[u].z + v[u].w*v[u].w;
    }
    #pragma unroll
    for (int o = 16; o > 0; o >>= 1) ss += __shfl_xor_sync(0xffffffffu, ss, o);
    float inv = 1.0f / fmaxf(sqrtf(ss), 1e-12f);
    #pragma unroll
    for (int u = 0; u < 4; u++) {
        __half2 h0 = __floats2half2_rn(v[u].x*inv, v[u].y*inv);
        __half2 h1 = __floats2half2_rn(v[u].z*inv, v[u].w*inv);
        uint2 w; w.x = *(uint32_t*)&h0; w.y = *(uint32_t*)&h1;
        ((uint2*)(g_Fh + (size_t)row * DD))[lane + u*32] = w;
    }
}

// ---------------------------------------------------------------------------
// K1: soft-topk weights + log(P_sup)
// ---------------------------------------------------------------------------
__global__ void k_weights(const float* __restrict__ slot_prob,
                          const float* __restrict__ slot_mask) {
    int b = blockIdx.x, m = threadIdx.x;
    __shared__ float sv[MM];
    __shared__ float red[MM];
    __shared__ int   topi[3];
    __shared__ float s_mean, s_zmax, s_zsum, s_wsum, s_tmax, s_tsum;

    float mask = slot_mask[m];
    float pv = slot_prob[b*MM + m] * mask;
    sv[m] = pv;
    __syncthreads();
    if (m == 0) {
        for (int t = 0; t < 3; t++) {
            float best = -INFINITY; int bi = 0;
            for (int i = 0; i < MM; i++) if (sv[i] > best) { best = sv[i]; bi = i; }
            topi[t] = bi; sv[bi] = -INFINITY;
        }
    }
    __syncthreads();
    float keep = (m == topi[0] || m == topi[1] || m == topi[2]) ? 1.f : 0.f;
    float q = pv * keep;
    red[m] = q; __syncthreads();
    if (m == 0) { float s = 0.f; for (int i = 0; i < MM; i++) s += red[i]; s_mean = s / (float)MM; }
    __syncthreads();
    float z = (q - s_mean) * 2.0f;
    red[m] = z; __syncthreads();
    if (m == 0) { float mx = -INFINITY; for (int i = 0; i < MM; i++) mx = fmaxf(mx, red[i]); s_zmax = mx; }
    __syncthreads();
    float e = expf(z - s_zmax);
    red[m] = e; __syncthreads();
    if (m == 0) { float s = 0.f; for (int i = 0; i < MM; i++) s += red[i]; s_zsum = s; }
    __syncthreads();
    float w = (e / s_zsum) * mask;
    red[m] = w; __syncthreads();
    if (m == 0) { float s = 0.f; for (int i = 0; i < MM; i++) s += red[i]; s_wsum = s; }
    __syncthreads();
    w = w / fmaxf(s_wsum, 1e-8f);
    g_w[b*MM + m] = w;

    float t = logf(w + 1e-8f) * (1.0f/1.6f);
    red[m] = t; __syncthreads();
    if (m == 0) { float mx = -INFINITY; for (int i = 0; i < MM; i++) mx = fmaxf(mx, red[i]); s_tmax = mx; }
    __syncthreads();
    float et = expf(t - s_tmax);
    red[m] = et; __syncthreads();
    if (m == 0) { float s = 0.f; for (int i = 0; i < MM; i++) s += red[i]; s_tsum = s; }
    __syncthreads();
    float lp = t - s_tmax - logf(s_tsum);
    g_lp[b*MM + m] = fmaxf(lp, -18.420680744f);
}

// ---------------------------------------------------------------------------
// K2: f16 HMMA GEMM + in-register class exp-sum.
// CTA = (batch-pair bp = bx>>1, proto-half = bx&1).
// A (128x512 f16, 2 batches) resident; B: 2048 protos streamed as 16 tiles
// of 128 protos x 8 chunks of 64 k, 3-stage cp.async.
// Warps 4(m) x 2(n); warp tile 32m x 64n (= one sorted class per warp slab).
// ---------------------------------------------------------------------------
#define ASTR_B  1040u       // A row stride bytes (520 f16)
#define BSTR_B  144u        // B row stride bytes (72 f16)
#define OFF_A   0u          // 128 rows x 1040 B = 133120
#define OFF_B   133120u
#define B_BUF   18432u      // 128 rows x 144 B
#define OFF_PART 188416u    // [128][5] f32 = 2560
#define OFF_CLS  190976u    // [4096] u8
#define SMEM_EVI 195072

// chunk q: nt = q>>3 (128-proto tile), dc = q&7 (64-k chunk)
__device__ __forceinline__ void load_Bchunk(uint32_t base, int half, int q, int tid) {
    const int nt = q >> 3, dc = q & 7;
    const __half* src0 = g_Ch + (size_t)(half*2048 + nt*128)*DD + dc*64;
    #pragma unroll
    for (int ii = 0; ii < 4; ii++) {
        int i = tid + ii*256;
        int n = i >> 3, g = i & 7;
        cp16(base + (uint32_t)n*BSTR_B + (uint32_t)g*16, src0 + (size_t)n*DD + g*8);
    }
}

__global__ void __launch_bounds__(256, 1)
k_evi() {
    extern __shared__ __align__(1024) char smem[];
    uint32_t smem_base = smem_to_u32(smem);
    const int tid = threadIdx.x, wid = tid >> 5, lane = tid & 31;
    const int bp = blockIdx.x >> 1, half = blockIdx.x & 1;
    const int wr = wid & 3, wc = wid >> 2;     // 4 row-groups x 2 col-groups

    float*   part  = (float*)(smem + OFF_PART);   // [128][5]
    uint8_t* cls_s = (uint8_t*)(smem + OFF_CLS);

    // cls bytes
    cp16(smem_base + OFF_CLS + (uint32_t)tid*16, g_clsSorted + tid*16);

    // resident A (128 x 512 f16, stride 520) — batches 2bp, 2bp+1
    #pragma unroll
    for (int ii = 0; ii < 32; ii++) {
        int i = tid + ii*256;
        int r = i >> 6, g = i & 63;
        const __half* src = g_Fh + ((size_t)(bp*2)*MM + r)*DD + g*8;
        cp16(smem_base + OFF_A + (uint32_t)r*ASTR_B + (uint32_t)g*16, src);
    }
    load_Bchunk(smem_base + OFF_B, half, 0, tid);
    cp_commit();
    load_Bchunk(smem_base + OFF_B + B_BUF, half, 1, tid);
    cp_commit();

    const uint32_t aBase = smem_base + OFF_A
        + (uint32_t)(wr*32 + (lane & 15))*ASTR_B + (uint32_t)(lane >> 4)*16;
    const uint32_t bLane = (uint32_t)((lane & 7) + ((lane >> 4) << 3))*BSTR_B
        + (uint32_t)((lane >> 3) & 1)*16;

    float acc[2][8][4];
    int bufsel = 0;     // q % 3

    for (int q = 0; q < 128; ++q) {
        const int nt = q >> 3, dc = q & 7;
        if (q < 126) cp_wait1(); else cp_wait0();
        __syncthreads();

        if (q + 2 < 128) {
            int nb = bufsel + 2; if (nb >= 3) nb -= 3;
            load_Bchunk(smem_base + OFF_B + (uint32_t)nb*B_BUF, half, q + 2, tid);
            cp_commit();
        }

        if (dc == 0) {
            #pragma unroll
            for (int m = 0; m < 2; m++)
                #pragma unroll
                for (int nf = 0; nf < 8; nf++)
                    #pragma unroll
                    for (int j = 0; j < 4; j++) acc[m][nf][j] = 0.f;
        }

        const uint32_t bBuf = smem_base + OFF_B + (uint32_t)bufsel*B_BUF
                            + (uint32_t)(wc*64)*BSTR_B + bLane;
        #pragma unroll
        for (int ks = 0; ks < 4; ++ks) {
            uint32_t a0[4], a1[4];
            uint32_t kb = (uint32_t)(dc*64 + ks*16)*2;
            ldm_x4(a0, aBase + kb);
            ldm_x4(a1, aBase + 16*ASTR_B + kb);
            uint32_t bf0[4], bf1[4], bf2[4], bf3[4];
            uint32_t bAddr = bBuf + (uint32_t)ks*32;
            ldm_x4(bf0, bAddr);
            ldm_x4(bf1, bAddr + 16*BSTR_B);
            ldm_x4(bf2, bAddr + 32*BSTR_B);
            ldm_x4(bf3, bAddr + 48*BSTR_B);
            mma16816(acc[0][0], a0, bf0[0], bf0[1]);
            mma16816(acc[0][1], a0, bf0[2], bf0[3]);
            mma16816(acc[0][2], a0, bf1[0], bf1[1]);
            mma16816(acc[0][3], a0, bf1[2], bf1[3]);
            mma16816(acc[0][4], a0, bf2[0], bf2[1]);
            mma16816(acc[0][5], a0, bf2[2], bf2[3]);
            mma16816(acc[0][6], a0, bf3[0], bf3[1]);
            mma16816(acc[0][7], a0, bf3[2], bf3[3]);
            mma16816(acc[1][0], a1, bf0[0], bf0[1]);
            mma16816(acc[1][1], a1, bf0[2], bf0[3]);
            mma16816(acc[1][2], a1, bf1[0], bf1[1]);
            mma16816(acc[1][3], a1, bf1[2], bf1[3]);
            mma16816(acc[1][4], a1, bf2[0], bf2[1]);
            mma16816(acc[1][5], a1, bf2[2], bf2[3]);
            mma16816(acc[1][6], a1, bf3[0], bf3[1]);
            mma16816(acc[1][7], a1, bf3[2], bf3[3]);
        }

        if (dc == 7) {
            // in-register exp + row reduce over this warp's 64 cols (one class)
            #pragma unroll
            for (int m = 0; m < 2; m++) {
                #pragma unroll
                for (int h = 0; h < 2; h++) {
                    float s = 0.f;
                    #pragma unroll
                    for (int nf = 0; nf < 8; nf++) {
                        s += __expf(2.0f * acc[m][nf][h*2 + 0]);
                        s += __expf(2.0f * acc[m][nf][h*2 + 1]);
                    }
                    s += __shfl_xor_sync(0xffffffffu, s, 1);
                    s += __shfl_xor_sync(0xffffffffu, s, 2);
                    if ((lane & 3) == 0) {
                        int row = wr*32 + m*16 + h*8 + (lane >> 2);
                        part[row*5 + wc] = s;
                    }
                }
            }
            __syncthreads();
            if (tid < 128) {
                int batch = bp*2 + (tid >> 6), slot = tid & 63;
                float* dst = g_evi + ((size_t)batch*MM + slot)*CC;
                #pragma unroll
                for (int j = 0; j < 2; ++j) {
                    int c = (int)cls_s[half*2048 + nt*128 + j*64];
                    dst[c] = 0.5f * logf(fmaxf(part[tid*5 + j], 1e-8f));
                }
            }
        }
        if (++bufsel == 3) bufsel = 0;
    }
}

// ---------------------------------------------------------------------------
// K3: epilogue per batch (top1, cosines vs top1 slots, support LSE)
// ---------------------------------------------------------------------------
__global__ void __launch_bounds__(256, 1)
k_out(const float* __restrict__ S_slots,
      const float* __restrict__ alpha,
      float* __restrict__ out) {
    extern __shared__ float sm[];
    float* s_s   = sm;                        // [512][68]
    float* tf_s  = s_s  + DD*SSTRIDE;         // [256][68]; reused as sup_s
    float* evi_s = tf_s + 256*SSTRIDE;        // [64*64]
    float* w_s   = evi_s + MM*CC;
    float* lp_s  = w_s + MM;
    float* t1v   = lp_s + MM;
    int*   t1i   = (int*)(t1v + MM);

    int b = blockIdx.x, tid = threadIdx.x;
    int wid = tid >> 5, lane = tid & 31;

    for (int i = tid; i < MM*CC; i += 256) evi_s[i] = g_evi[(size_t)b*MM*CC + i];
    if (tid < MM) { w_s[tid] = g_w[b*MM + tid]; lp_s[tid] = g_lp[b*MM + tid]; }

    const float* sb = S_slots + (size_t)b*MM*DD;
    for (int rr = 0; rr < 8; rr++) {
        int r = wid*8 + rr;
        const float4* rp = (const float4*)(sb + r*DD);
        float4 v[4]; float ss = 0.f;
        #pragma unroll
        for (int u = 0; u < 4; u++) {
            v[u] = rp[u*32 + lane];
            ss += v[u].x*v[u].x + v[u].y*v[u].y + v[u].z*v[u].z + v[u].w*v[u].w;
        }
        #pragma unroll
        for (int o = 16; o > 0; o >>= 1) ss += __shfl_xor_sync(0xffffffffu, ss, o);
        float inv = 1.0f / fmaxf(sqrtf(ss), 1e-12f);
        #pragma unroll
        for (int u = 0; u < 4; u++) {
            int d0 = u*128 + lane*4;
            s_s[(d0+0)*SSTRIDE + r] = v[u].x * inv;
            s_s[(d0+1)*SSTRIDE + r] = v[u].y * inv;
            s_s[(d0+2)*SSTRIDE + r] = v[u].z * inv;
            s_s[(d0+3)*SSTRIDE + r] = v[u].w * inv;
        }
    }
    __syncthreads();

    if (tid < CC) {
        int c = tid;
        float best = -INFINITY; int bi = 0;
        for (int m = 0; m < MM; m++) {
            float sc = evi_s[m*CC + c] * w_s[m];
            if (sc > best) { best = sc; bi = m; }
        }
        t1v[c] = best; t1i[c] = bi;
    }
    __syncthreads();

    int tr = tid >> 4, tc = tid & 15;
    int gc = tid >> 2, gq = tid & 3;
    float acc[4][4] = {};
    #pragma unroll 1
    for (int h = 0; h < 2; h++) {
        __syncthreads();
        {
            int src = t1i[gc];
            for (int u = 0; u < 64; u++) {
                int k = gq*64 + u;
                tf_s[k*SSTRIDE + gc] = s_s[(h*256 + k)*SSTRIDE + src];
            }
        }
        __syncthreads();
        const float* fp = s_s  + h*256*SSTRIDE + tr*4;
        const float* gp = tf_s + tc*4;
        #pragma unroll 4
        for (int k = 0; k < 256; k++) {
            float4 fv = *(const float4*)(fp + k*SSTRIDE);
            float4 gv = *(const float4*)(gp + k*SSTRIDE);
            acc[0][0] = fmaf(fv.x, gv.x, acc[0][0]);
            acc[0][1] = fmaf(fv.x, gv.y, acc[0][1]);
            acc[0][2] = fmaf(fv.x, gv.z, acc[0][2]);
            acc[0][3] = fmaf(fv.x, gv.w, acc[0][3]);
            acc[1][0] = fmaf(fv.y, gv.x, acc[1][0]);
            acc[1][1] = fmaf(fv.y, gv.y, acc[1][1]);
            acc[1][2] = fmaf(fv.y, gv.z, acc[1][2]);
            acc[1][3] = fmaf(fv.y, gv.w, acc[1][3]);
            acc[2][0] = fmaf(fv.z, gv.x, acc[2][0]);
            acc[2][1] = fmaf(fv.z, gv.y, acc[2][1]);
            acc[2][2] = fmaf(fv.z, gv.z, acc[2][2]);
            acc[2][3] = fmaf(fv.z, gv.w, acc[2][3]);
            acc[3][0] = fmaf(fv.w, gv.x, acc[3][0]);
            acc[3][1] = fmaf(fv.w, gv.y, acc[3][1]);
            acc[3][2] = fmaf(fv.w, gv.z, acc[3][2]);
            acc[3][3] = fmaf(fv.w, gv.w, acc[3][3]);
        }
    }
    __syncthreads();
    float* sup_s = tf_s;
    #pragma unroll
    for (int i = 0; i < 4; i++) {
        #pragma unroll
        for (int j = 0; j < 4; j++) {
            int m = tr*4 + i, c = tc*4 + j;
            float cosv = fmaxf(acc[i][j], 0.f);
            float sr = evi_s[m*CC + c] + lp_s[m] - cosv;
            if (m == t1i[c]) sr = -10000.0f;
            sup_s[m*CC + c] = sr;
        }
    }
    __syncthreads();
    if (tid < CC) {
        int c = tid;
        float mx = -INFINITY;
        for (int m = 0; m < MM; m++) mx = fmaxf(mx, sup_s[m*CC + c]);
        float sum = 0.f;
        for (int m = 0; m < MM; m++) sum += expf(sup_s[m*CC + c] - mx);
        float sval = mx + logf(sum);
        out[b*CC + c] = alpha[0] * (t1v[c] + 0.4f * sval);
    }
}

// ---------------------------------------------------------------------------
extern "C" void kernel_launch(void* const* d_in, const int* in_sizes, int n_in,
                              void* d_out, int out_size) {
    const float* feats     = (const float*)d_in[0];
    const float* slot_prob = (const float*)d_in[1];
    const float* slot_mask = (const float*)d_in[2];
    const float* S_slots   = (const float*)d_in[3];
    const float* Cmat      = (const float*)d_in[4];
    const int*   Ccls      = (const int*)d_in[5];
    const float* alpha     = (const float*)d_in[6];
    float* out = (float*)d_out;

    const int smem3 = (DD*SSTRIDE + 256*SSTRIDE + MM*CC + 3*MM) * 4 + MM * 4;

    cudaFuncSetAttribute(k_evi, cudaFuncAttributeMaxDynamicSharedMemorySize, SMEM_EVI);
    cudaFuncSetAttribute(k_out, cudaFuncAttributeMaxDynamicSharedMemorySize, smem3);

    k_weights<<<BB, MM>>>(slot_prob, slot_mask);
    k_perm<<<KK/256, 256>>>(Ccls);
    prep_C<<<KK*DD/1024, 256>>>(Cmat);
    prep_F<<<BB*MM/8, 256>>>(feats);
    k_evi<<<BB, 256, SMEM_EVI>>>();
    k_out<<<BB, 256, smem3>>>(S_slots, alpha, out);
}

// round 7
// speedup vs baseline: 9.1441x; 1.0498x over previous
#include <cuda_runtime.h>
#include <cuda_fp16.h>
#include <math.h>
#include <stdint.h>

#define BB 128
#define MM 64
#define DD 512
#define KK 4096
#define CC 64
#define SSTRIDE 68

// ---------------------------------------------------------------------------
// scratch (__device__ globals per allocation-free rule)
// ---------------------------------------------------------------------------
__device__ __align__(16) __half g_Fh[BB*MM*DD];   // normalized feats, f16
__device__ __align__(16) __half g_Ch[KK*DD];      // C, f16, class-sorted rows
__device__ int     g_rank[KK];
__device__ uint8_t g_clsSorted[KK];
__device__ float   g_evi[BB*MM*CC];
__device__ float   g_w[BB*MM];
__device__ float   g_lp[BB*MM];

// ---------------------------------------------------------------------------
__device__ __forceinline__ uint32_t smem_to_u32(const void* p) {
    uint32_t a;
    asm("{ .reg .u64 t; cvta.to.shared.u64 t, %1; cvt.u32.u64 %0, t; }" : "=r"(a) : "l"(p));
    return a;
}
__device__ __forceinline__ void cp16(uint32_t dst, const void* src) {
    asm volatile("cp.async.cg.shared.global [%0], [%1], 16;" :: "r"(dst), "l"(src));
}
__device__ __forceinline__ void cp_commit() { asm volatile("cp.async.commit_group;" ::: "memory"); }
__device__ __forceinline__ void cp_wait0()  { asm volatile("cp.async.wait_group 0;" ::: "memory"); }
__device__ __forceinline__ void cp_wait1()  { asm volatile("cp.async.wait_group 1;" ::: "memory"); }

__device__ __forceinline__ void ldm_x4(uint32_t r[4], uint32_t addr) {
    asm volatile("ldmatrix.sync.aligned.m8n8.x4.shared.b16 {%0,%1,%2,%3}, [%4];"
        : "=r"(r[0]), "=r"(r[1]), "=r"(r[2]), "=r"(r[3]) : "r"(addr));
}
__device__ __forceinline__ void mma16816(float* c, const uint32_t* a, uint32_t b0, uint32_t b1) {
    asm volatile(
        "mma.sync.aligned.m16n8k16.row.col.f32.f16.f16.f32 "
        "{%0,%1,%2,%3}, {%4,%5,%6,%7}, {%8,%9}, {%0,%1,%2,%3};"
        : "+f"(c[0]), "+f"(c[1]), "+f"(c[2]), "+f"(c[3])
        : "r"(a[0]), "r"(a[1]), "r"(a[2]), "r"(a[3]), "r"(b0), "r"(b1));
}

// ---------------------------------------------------------------------------
// k_perm: deterministic stable class-sort ranks (grid 16, block 256)
// ---------------------------------------------------------------------------
__global__ void k_perm(const int* __restrict__ Ccls) {
    __shared__ int cls_s[KK];
    int tid = threadIdx.x;
    for (int i = tid; i < KK; i += 256) cls_s[i] = Ccls[i] & 63;
    __syncthreads();
    int i = blockIdx.x * 256 + tid;
    int ci = cls_s[i];
    int rank = 0;
    for (int j = 0; j < KK; j++) {
        int cj = cls_s[j];
        rank += (cj < ci) || (cj == ci && j < i);
    }
    g_rank[i] = rank;
    g_clsSorted[rank] = (uint8_t)ci;
}

// prep_C: fp32 -> f16, scatter rows to class-sorted positions
__global__ void prep_C(const float* __restrict__ Cmat) {
    long i = (long)blockIdx.x * 256 + threadIdx.x;      // over float4s
    int row = (int)(i >> 7), col4 = (int)(i & 127);
    float4 v = ((const float4*)Cmat)[i];
    int r = g_rank[row];
    __half2 h0 = __floats2half2_rn(v.x, v.y);
    __half2 h1 = __floats2half2_rn(v.z, v.w);
    uint2 u; u.x = *(uint32_t*)&h0; u.y = *(uint32_t*)&h1;
    ((uint2*)(g_Ch + (size_t)r * DD))[col4] = u;
}

// prep_F: l2-normalize rows of feats, f16. One warp per row.
__global__ void prep_F(const float* __restrict__ feats) {
    int row = blockIdx.x * 8 + (threadIdx.x >> 5);
    int lane = threadIdx.x & 31;
    const float4* rp = (const float4*)(feats + (size_t)row * DD);
    float4 v[4]; float ss = 0.f;
    #pragma unroll
    for (int u = 0; u < 4; u++) {
        v[u] = rp[lane + u*32];
        ss += v[u].x*v[u].x + v[u].y*v[u].y + v[u].z*v[u].z + v[u].w*v[u].w;
    }
    #pragma unroll
    for (int o = 16; o > 0; o >>= 1) ss += __shfl_xor_sync(0xffffffffu, ss, o);
    float inv = 1.0f / fmaxf(sqrtf(ss), 1e-12f);
    #pragma unroll
    for (int u = 0; u < 4; u++) {
        __half2 h0 = __floats2half2_rn(v[u].x*inv, v[u].y*inv);
        __half2 h1 = __floats2half2_rn(v[u].z*inv, v[u].w*inv);
        uint2 w; w.x = *(uint32_t*)&h0; w.y = *(uint32_t*)&h1;
        ((uint2*)(g_Fh + (size_t)row * DD))[lane + u*32] = w;
    }
}

// ---------------------------------------------------------------------------
// K1: soft-topk weights + log(P_sup)
// ---------------------------------------------------------------------------
__global__ void k_weights(const float* __restrict__ slot_prob,
                          const float* __restrict__ slot_mask) {
    int b = blockIdx.x, m = threadIdx.x;
    __shared__ float sv[MM];
    __shared__ float red[MM];
    __shared__ int   topi[3];
    __shared__ float s_mean, s_zmax, s_zsum, s_wsum, s_tmax, s_tsum;

    float mask = slot_mask[m];
    float pv = slot_prob[b*MM + m] * mask;
    sv[m] = pv;
    __syncthreads();
    if (m == 0) {
        for (int t = 0; t < 3; t++) {
            float best = -INFINITY; int bi = 0;
            for (int i = 0; i < MM; i++) if (sv[i] > best) { best = sv[i]; bi = i; }
            topi[t] = bi; sv[bi] = -INFINITY;
        }
    }
    __syncthreads();
    float keep = (m == topi[0] || m == topi[1] || m == topi[2]) ? 1.f : 0.f;
    float q = pv * keep;
    red[m] = q; __syncthreads();
    if (m == 0) { float s = 0.f; for (int i = 0; i < MM; i++) s += red[i]; s_mean = s / (float)MM; }
    __syncthreads();
    float z = (q - s_mean) * 2.0f;
    red[m] = z; __syncthreads();
    if (m == 0) { float mx = -INFINITY; for (int i = 0; i < MM; i++) mx = fmaxf(mx, red[i]); s_zmax = mx; }
    __syncthreads();
    float e = expf(z - s_zmax);
    red[m] = e; __syncthreads();
    if (m == 0) { float s = 0.f; for (int i = 0; i < MM; i++) s += red[i]; s_zsum = s; }
    __syncthreads();
    float w = (e / s_zsum) * mask;
    red[m] = w; __syncthreads();
    if (m == 0) { float s = 0.f; for (int i = 0; i < MM; i++) s += red[i]; s_wsum = s; }
    __syncthreads();
    w = w / fmaxf(s_wsum, 1e-8f);
    g_w[b*MM + m] = w;

    float t = logf(w + 1e-8f) * (1.0f/1.6f);
    red[m] = t; __syncthreads();
    if (m == 0) { float mx = -INFINITY; for (int i = 0; i < MM; i++) mx = fmaxf(mx, red[i]); s_tmax = mx; }
    __syncthreads();
    float et = expf(t - s_tmax);
    red[m] = et; __syncthreads();
    if (m == 0) { float s = 0.f; for (int i = 0; i < MM; i++) s += red[i]; s_tsum = s; }
    __syncthreads();
    float lp = t - s_tmax - logf(s_tsum);
    g_lp[b*MM + m] = fmaxf(lp, -18.420680744f);
}

// ---------------------------------------------------------------------------
// K2: f16 HMMA GEMM + in-register class exp-sum. 512 threads.
// CTA = (batch-pair bp = bx>>1, proto-half = bx&1).
// A (128x512 f16, 2 batches) resident; B: 2048 protos streamed as 8 tiles
// of 256 protos x 8 chunks of 64 k, 2-stage cp.async double buffer.
// Warps 4(m) x 4(n); warp tile 32m x 64n (= one sorted class per warp slab).
// ---------------------------------------------------------------------------
#define THREADS 512
#define ASTR_B  1040u       // A row stride bytes (520 f16)
#define BSTR_B  144u        // B row stride bytes (72 f16)
#define OFF_A   0u          // 128 rows x 1040 B = 133120
#define OFF_B   133120u
#define B_BUF   36864u      // 256 rows x 144 B
#define OFF_PART 206848u    // [128][5] f32 = 2560
#define OFF_CLS  209408u    // [4096] u8
#define SMEM_EVI 213504

// chunk q: nt = q>>3 (256-proto tile), dc = q&7 (64-k chunk)
__device__ __forceinline__ void load_Bchunk(uint32_t base, int half, int q, int tid) {
    const int nt = q >> 3, dc = q & 7;
    const __half* src0 = g_Ch + (size_t)(half*2048 + nt*256)*DD + dc*64;
    #pragma unroll
    for (int ii = 0; ii < 4; ii++) {
        int i = tid + ii*THREADS;
        int n = i >> 3, g = i & 7;
        cp16(base + (uint32_t)n*BSTR_B + (uint32_t)g*16, src0 + (size_t)n*DD + g*8);
    }
}

__global__ void __launch_bounds__(THREADS, 1)
k_evi() {
    extern __shared__ __align__(1024) char smem[];
    uint32_t smem_base = smem_to_u32(smem);
    const int tid = threadIdx.x, wid = tid >> 5, lane = tid & 31;
    const int bp = blockIdx.x >> 1, half = blockIdx.x & 1;
    const int wr = wid & 3, wc = wid >> 2;     // 4 row-groups x 4 col-groups

    float*   part  = (float*)(smem + OFF_PART);   // [128][5]
    uint8_t* cls_s = (uint8_t*)(smem + OFF_CLS);

    // cls bytes (4096 B)
    if (tid < 256) cp16(smem_base + OFF_CLS + (uint32_t)tid*16, g_clsSorted + tid*16);

    // resident A (128 x 512 f16, stride 520) — batches 2bp, 2bp+1
    #pragma unroll
    for (int ii = 0; ii < 16; ii++) {
        int i = tid + ii*THREADS;
        int r = i >> 6, g = i & 63;
        const __half* src = g_Fh + ((size_t)(bp*2)*MM + r)*DD + g*8;
        cp16(smem_base + OFF_A + (uint32_t)r*ASTR_B + (uint32_t)g*16, src);
    }
    load_Bchunk(smem_base + OFF_B, half, 0, tid);
    cp_commit();

    const uint32_t aBase = smem_base + OFF_A
        + (uint32_t)(wr*32 + (lane & 15))*ASTR_B + (uint32_t)(lane >> 4)*16;
    const uint32_t bLane = (uint32_t)((lane & 7) + ((lane >> 4) << 3))*BSTR_B
        + (uint32_t)((lane >> 3) & 1)*16;

    float acc[2][8][4];

    for (int q = 0; q < 64; ++q) {
        const int nt = q >> 3, dc = q & 7;

        __syncthreads();   // all warps done computing q-1 (its buffer now reusable)
        if (q + 1 < 64) {
            load_Bchunk(smem_base + OFF_B + (uint32_t)((q+1) & 1)*B_BUF, half, q + 1, tid);
            cp_commit();
            cp_wait1();    // q's buffer complete
        } else {
            cp_wait0();
        }
        __syncthreads();   // q's data visible to all warps

        if (dc == 0) {
            #pragma unroll
            for (int m = 0; m < 2; m++)
                #pragma unroll
                for (int nf = 0; nf < 8; nf++)
                    #pragma unroll
                    for (int j = 0; j < 4; j++) acc[m][nf][j] = 0.f;
        }

        const uint32_t bBuf = smem_base + OFF_B + (uint32_t)(q & 1)*B_BUF
                            + (uint32_t)(wc*64)*BSTR_B + bLane;
        #pragma unroll
        for (int ks = 0; ks < 4; ++ks) {
            uint32_t a0[4], a1[4];
            uint32_t kb = (uint32_t)(dc*64 + ks*16)*2;
            ldm_x4(a0, aBase + kb);
            ldm_x4(a1, aBase + 16*ASTR_B + kb);
            uint32_t bf0[4], bf1[4], bf2[4], bf3[4];
            uint32_t bAddr = bBuf + (uint32_t)ks*32;
            ldm_x4(bf0, bAddr);
            ldm_x4(bf1, bAddr + 16*BSTR_B);
            ldm_x4(bf2, bAddr + 32*BSTR_B);
            ldm_x4(bf3, bAddr + 48*BSTR_B);
            mma16816(acc[0][0], a0, bf0[0], bf0[1]);
            mma16816(acc[0][1], a0, bf0[2], bf0[3]);
            mma16816(acc[0][2], a0, bf1[0], bf1[1]);
            mma16816(acc[0][3], a0, bf1[2], bf1[3]);
            mma16816(acc[0][4], a0, bf2[0], bf2[1]);
            mma16816(acc[0][5], a0, bf2[2], bf2[3]);
            mma16816(acc[0][6], a0, bf3[0], bf3[1]);
            mma16816(acc[0][7], a0, bf3[2], bf3[3]);
            mma16816(acc[1][0], a1, bf0[0], bf0[1]);
            mma16816(acc[1][1], a1, bf0[2], bf0[3]);
            mma16816(acc[1][2], a1, bf1[0], bf1[1]);
            mma16816(acc[1][3], a1, bf1[2], bf1[3]);
            mma16816(acc[1][4], a1, bf2[0], bf2[1]);
            mma16816(acc[1][5], a1, bf2[2], bf2[3]);
            mma16816(acc[1][6], a1, bf3[0], bf3[1]);
            mma16816(acc[1][7], a1, bf3[2], bf3[3]);
        }

        if (dc == 7) {
            // in-register exp + row reduce over this warp's 64 cols (one class)
            #pragma unroll
            for (int m = 0; m < 2; m++) {
                #pragma unroll
                for (int h = 0; h < 2; h++) {
                    float s = 0.f;
                    #pragma unroll
                    for (int nf = 0; nf < 8; nf++) {
                        s += __expf(2.0f * acc[m][nf][h*2 + 0]);
                        s += __expf(2.0f * acc[m][nf][h*2 + 1]);
                    }
                    s += __shfl_xor_sync(0xffffffffu, s, 1);
                    s += __shfl_xor_sync(0xffffffffu, s, 2);
                    if ((lane & 3) == 0) {
                        int row = wr*32 + m*16 + h*8 + (lane >> 2);
                        part[row*5 + wc] = s;
                    }
                }
            }
            __syncthreads();
            if (tid < 128) {
                int batch = bp*2 + (tid >> 6), slot = tid & 63;
                float* dst = g_evi + ((size_t)batch*MM + slot)*CC;
                #pragma unroll
                for (int j = 0; j < 4; ++j) {
                    int c = (int)cls_s[half*2048 + nt*256 + j*64];
                    dst[c] = 0.5f * logf(fmaxf(part[tid*5 + j], 1e-8f));
                }
            }
        }
    }
}

// ---------------------------------------------------------------------------
// K3: epilogue per batch (top1, cosines vs top1 slots, support LSE)
// ---------------------------------------------------------------------------
__global__ void __launch_bounds__(256, 1)
k_out(const float* __restrict__ S_slots,
      const float* __restrict__ alpha,
      float* __restrict__ out) {
    extern __shared__ float sm[];
    float* s_s   = sm;                        // [512][68]
    float* tf_s  = s_s  + DD*SSTRIDE;         // [256][68]; reused as sup_s
    float* evi_s = tf_s + 256*SSTRIDE;        // [64*64]
    float* w_s   = evi_s + MM*CC;
    float* lp_s  = w_s + MM;
    float* t1v   = lp_s + MM;
    int*   t1i   = (int*)(t1v + MM);

    int b = blockIdx.x, tid = threadIdx.x;
    int wid = tid >> 5, lane = tid & 31;

    for (int i = tid; i < MM*CC; i += 256) evi_s[i] = g_evi[(size_t)b*MM*CC + i];
    if (tid < MM) { w_s[tid] = g_w[b*MM + tid]; lp_s[tid] = g_lp[b*MM + tid]; }

    const float* sb = S_slots + (size_t)b*MM*DD;
    for (int rr = 0; rr < 8; rr++) {
        int r = wid*8 + rr;
        const float4* rp = (const float4*)(sb + r*DD);
        float4 v[4]; float ss = 0.f;
        #pragma unroll
        for (int u = 0; u < 4; u++) {
            v[u] = rp[u*32 + lane];
            ss += v[u].x*v[u].x + v[u].y*v[u].y + v[u].z*v[u].z + v[u].w*v[u].w;
        }
        #pragma unroll
        for (int o = 16; o > 0; o >>= 1) ss += __shfl_xor_sync(0xffffffffu, ss, o);
        float inv = 1.0f / fmaxf(sqrtf(ss), 1e-12f);
        #pragma unroll
        for (int u = 0; u < 4; u++) {
            int d0 = u*128 + lane*4;
            s_s[(d0+0)*SSTRIDE + r] = v[u].x * inv;
            s_s[(d0+1)*SSTRIDE + r] = v[u].y * inv;
            s_s[(d0+2)*SSTRIDE + r] = v[u].z * inv;
            s_s[(d0+3)*SSTRIDE + r] = v[u].w * inv;
        }
    }
    __syncthreads();

    if (tid < CC) {
        int c = tid;
        float best = -INFINITY; int bi = 0;
        for (int m = 0; m < MM; m++) {
            float sc = evi_s[m*CC + c] * w_s[m];
            if (sc > best) { best = sc; bi = m; }
        }
        t1v[c] = best; t1i[c] = bi;
    }
    __syncthreads();

    int tr = tid >> 4, tc = tid & 15;
    int gc = tid >> 2, gq = tid & 3;
    float acc[4][4] = {};
    #pragma unroll 1
    for (int h = 0; h < 2; h++) {
        __syncthreads();
        {
            int src = t1i[gc];
            for (int u = 0; u < 64; u++) {
                int k = gq*64 + u;
                tf_s[k*SSTRIDE + gc] = s_s[(h*256 + k)*SSTRIDE + src];
            }
        }
        __syncthreads();
        const float* fp = s_s  + h*256*SSTRIDE + tr*4;
        const float* gp = tf_s + tc*4;
        #pragma unroll 4
        for (int k = 0; k < 256; k++) {
            float4 fv = *(const float4*)(fp + k*SSTRIDE);
            float4 gv = *(const float4*)(gp + k*SSTRIDE);
            acc[0][0] = fmaf(fv.x, gv.x, acc[0][0]);
            acc[0][1] = fmaf(fv.x, gv.y, acc[0][1]);
            acc[0][2] = fmaf(fv.x, gv.z, acc[0][2]);
            acc[0][3] = fmaf(fv.x, gv.w, acc[0][3]);
            acc[1][0] = fmaf(fv.y, gv.x, acc[1][0]);
            acc[1][1] = fmaf(fv.y, gv.y, acc[1][1]);
            acc[1][2] = fmaf(fv.y, gv.z, acc[1][2]);
            acc[1][3] = fmaf(fv.y, gv.w, acc[1][3]);
            acc[2][0] = fmaf(fv.z, gv.x, acc[2][0]);
            acc[2][1] = fmaf(fv.z, gv.y, acc[2][1]);
            acc[2][2] = fmaf(fv.z, gv.z, acc[2][2]);
            acc[2][3] = fmaf(fv.z, gv.w, acc[2][3]);
            acc[3][0] = fmaf(fv.w, gv.x, acc[3][0]);
            acc[3][1] = fmaf(fv.w, gv.y, acc[3][1]);
            acc[3][2] = fmaf(fv.w, gv.z, acc[3][2]);
            acc[3][3] = fmaf(fv.w, gv.w, acc[3][3]);
        }
    }
    __syncthreads();
    float* sup_s = tf_s;
    #pragma unroll
    for (int i = 0; i < 4; i++) {
        #pragma unroll
        for (int j = 0; j < 4; j++) {
            int m = tr*4 + i, c = tc*4 + j;
            float cosv = fmaxf(acc[i][j], 0.f);
            float sr = evi_s[m*CC + c] + lp_s[m] - cosv;
            if (m == t1i[c]) sr = -10000.0f;
            sup_s[m*CC + c] = sr;
        }
    }
    __syncthreads();
    if (tid < CC) {
        int c = tid;
        float mx = -INFINITY;
        for (int m = 0; m < MM; m++) mx = fmaxf(mx, sup_s[m*CC + c]);
        float sum = 0.f;
        for (int m = 0; m < MM; m++) sum += expf(sup_s[m*CC + c] - mx);
        float sval = mx + logf(sum);
        out[b*CC + c] = alpha[0] * (t1v[c] + 0.4f * sval);
    }
}

// ---------------------------------------------------------------------------
extern "C" void kernel_launch(void* const* d_in, const int* in_sizes, int n_in,
                              void* d_out, int out_size) {
    const float* feats     = (const float*)d_in[0];
    const float* slot_prob = (const float*)d_in[1];
    const float* slot_mask = (const float*)d_in[2];
    const float* S_slots   = (const float*)d_in[3];
    const float* Cmat      = (const float*)d_in[4];
    const int*   Ccls      = (const int*)d_in[5];
    const float* alpha     = (const float*)d_in[6];
    float* out = (float*)d_out;

    const int smem3 = (DD*SSTRIDE + 256*SSTRIDE + MM*CC + 3*MM) * 4 + MM * 4;

    cudaFuncSetAttribute(k_evi, cudaFuncAttributeMaxDynamicSharedMemorySize, SMEM_EVI);
    cudaFuncSetAttribute(k_out, cudaFuncAttributeMaxDynamicSharedMemorySize, smem3);

    k_weights<<<BB, MM>>>(slot_prob, slot_mask);
    k_perm<<<KK/256, 256>>>(Ccls);
    prep_C<<<KK*DD/1024, 256>>>(Cmat);
    prep_F<<<BB*MM/8, 256>>>(feats);
    k_evi<<<BB, THREADS, SMEM_EVI>>>();
    k_out<<<BB, 256, smem3>>>(S_slots, alpha, out);
}